// round 1
// baseline (speedup 1.0000x reference)
#include <cuda_runtime.h>

#define NODES 25000
#define EDGES 150000
#define DIM   512
#define HEADS 8

// ---------------- scratch (device globals: no runtime allocation) ----------
__device__ float g_K[NODES * DIM];
__device__ float g_Q[NODES * DIM];
__device__ float g_V[NODES * DIM];
__device__ float g_E[EDGES * HEADS];   // exp(score) per edge-head
__device__ float g_S[NODES * HEADS];   // segment sums (softmax denom)
__device__ float g_AGG[NODES * DIM];   // aggregated messages

// ---------------- zero scratch that gets atomically accumulated -----------
__global__ void zero_scratch() {
    int i = blockIdx.x * blockDim.x + threadIdx.x;
    if (i < NODES * DIM)   g_AGG[i] = 0.0f;
    if (i < NODES * HEADS) g_S[i]   = 0.0f;
}

// ---------------- classic 128x128x8 SGEMM with bias (fp32) ----------------
// C[M,N] = A[M,K] @ B[K,N] + bias[N].  N,K multiples of 128/8; M edge guarded.
__global__ __launch_bounds__(256) void sgemm_bias(
    const float* __restrict__ A, const float* __restrict__ B,
    const float* __restrict__ bias, float* __restrict__ C,
    int M, int N, int K)
{
    __shared__ float As[8][128];   // transposed A tile: As[k][m]
    __shared__ float Bs[8][128];

    const int tid = threadIdx.x;
    const int bx = blockIdx.x, by = blockIdx.y;
    const int rowBase = by * 128;

    const int aRow = tid >> 1;            // 0..127
    const int aCol = (tid & 1) * 4;       // 0 or 4
    const int bRow = tid >> 5;            // 0..7
    const int bCol = (tid & 31) * 4;      // 0..124

    const int tx = tid & 15, ty = tid >> 4;

    float acc[8][8];
#pragma unroll
    for (int i = 0; i < 8; i++)
#pragma unroll
        for (int j = 0; j < 8; j++) acc[i][j] = 0.0f;

    const bool aValid = (rowBase + aRow) < M;
    const float* Aptr = A + (size_t)(rowBase + aRow) * K + aCol;
    const float* Bptr = B + (size_t)bRow * N + bx * 128 + bCol;

    for (int k0 = 0; k0 < K; k0 += 8) {
        float4 av = aValid ? *(const float4*)(Aptr + k0)
                           : make_float4(0.f, 0.f, 0.f, 0.f);
        As[aCol + 0][aRow] = av.x;
        As[aCol + 1][aRow] = av.y;
        As[aCol + 2][aRow] = av.z;
        As[aCol + 3][aRow] = av.w;
        *(float4*)&Bs[bRow][bCol] = *(const float4*)(Bptr + (size_t)k0 * N);
        __syncthreads();

#pragma unroll
        for (int kk = 0; kk < 8; kk++) {
            float ar[8], br[8];
#pragma unroll
            for (int i = 0; i < 8; i++) ar[i] = As[kk][ty * 8 + i];
#pragma unroll
            for (int j = 0; j < 8; j++) br[j] = Bs[kk][tx * 8 + j];
#pragma unroll
            for (int i = 0; i < 8; i++)
#pragma unroll
                for (int j = 0; j < 8; j++) acc[i][j] += ar[i] * br[j];
        }
        __syncthreads();
    }

#pragma unroll
    for (int i = 0; i < 8; i++) {
        int row = rowBase + ty * 8 + i;
        if (row >= M) continue;
#pragma unroll
        for (int j = 0; j < 8; j += 4) {
            int col = bx * 128 + tx * 8 + j;
            float4 o;
            o.x = acc[i][j + 0] + bias[col + 0];
            o.y = acc[i][j + 1] + bias[col + 1];
            o.z = acc[i][j + 2] + bias[col + 2];
            o.w = acc[i][j + 3] + bias[col + 3];
            *(float4*)&C[(size_t)row * N + col] = o;
        }
    }
}

// ---------------- edge scores: warp per edge ------------------------------
// lane l: head h = l/4, quarter part = l%4 (16 dims each).
// score = dot(Q[recv,h], K[send,h]) / 8 ; e = exp(score) (shift cancels in
// the segment softmax, and scores are O(1) here so no overflow risk).
__global__ void edge_attn(const int* __restrict__ send,
                          const int* __restrict__ recv)
{
    int g = blockIdx.x * blockDim.x + threadIdx.x;
    int m = g >> 5;
    if (m >= EDGES) return;
    int lane = g & 31;
    int h = lane >> 2, part = lane & 3;
    int s = send[m], r = recv[m];

    const float4* q = (const float4*)&g_Q[(size_t)r * DIM + h * 64 + part * 16];
    const float4* k = (const float4*)&g_K[(size_t)s * DIM + h * 64 + part * 16];
    float acc = 0.0f;
#pragma unroll
    for (int i = 0; i < 4; i++) {
        float4 a = q[i], b = k[i];
        acc += a.x * b.x + a.y * b.y + a.z * b.z + a.w * b.w;
    }
    acc += __shfl_xor_sync(0xffffffffu, acc, 1);
    acc += __shfl_xor_sync(0xffffffffu, acc, 2);
    if (part == 0) {
        float e = __expf(acc * 0.125f);
        g_E[m * HEADS + h] = e;
        atomicAdd(&g_S[r * HEADS + h], e);
    }
}

// ---------------- weighted message scatter-add: warp per edge -------------
__global__ void scatter_msg(const int* __restrict__ send,
                            const int* __restrict__ recv)
{
    int g = blockIdx.x * blockDim.x + threadIdx.x;
    int m = g >> 5;
    if (m >= EDGES) return;
    int lane = g & 31;
    int h = lane >> 2, part = lane & 3;
    int s = send[m], r = recv[m];

    float w = g_E[m * HEADS + h] / g_S[r * HEADS + h];  // denom >= this e > 0

    const float4* v = (const float4*)&g_V[(size_t)s * DIM + h * 64 + part * 16];
    float* dst = &g_AGG[(size_t)r * DIM + h * 64 + part * 16];
#pragma unroll
    for (int i = 0; i < 4; i++) {
        float4 mv = v[i];
        mv.x *= w; mv.y *= w; mv.z *= w; mv.w *= w;
        asm volatile("red.global.add.v4.f32 [%0], {%1, %2, %3, %4};"
                     :: "l"(dst + i * 4),
                        "f"(mv.x), "f"(mv.y), "f"(mv.z), "f"(mv.w)
                     : "memory");
    }
}

// ---------------------------------------------------------------------------
extern "C" void kernel_launch(void* const* d_in, const int* in_sizes, int n_in,
                              void* d_out, int out_size) {
    const float* x   = (const float*)d_in[0];
    const int*  eidx = (const int*)  d_in[1];
    const float* Wk  = (const float*)d_in[2];
    const float* bk  = (const float*)d_in[3];
    const float* Wq  = (const float*)d_in[4];
    const float* bq  = (const float*)d_in[5];
    const float* Wv  = (const float*)d_in[6];
    const float* bv  = (const float*)d_in[7];
    const float* Wff = (const float*)d_in[8];
    const float* bff = (const float*)d_in[9];
    float* out = (float*)d_out;

    const int* send = eidx;          // edge_index[0] = senders
    const int* recv = eidx + EDGES;  // edge_index[1] = receivers

    float *Kp, *Qp, *Vp, *Ap;
    cudaGetSymbolAddress((void**)&Kp, g_K);
    cudaGetSymbolAddress((void**)&Qp, g_Q);
    cudaGetSymbolAddress((void**)&Vp, g_V);
    cudaGetSymbolAddress((void**)&Ap, g_AGG);

    dim3 gemmGrid(DIM / 128, (NODES + 127) / 128);

    zero_scratch<<<(NODES * DIM + 255) / 256, 256>>>();

    sgemm_bias<<<gemmGrid, 256>>>(x, Wk, bk, Kp, NODES, DIM, DIM);
    sgemm_bias<<<gemmGrid, 256>>>(x, Wq, bq, Qp, NODES, DIM, DIM);
    sgemm_bias<<<gemmGrid, 256>>>(x, Wv, bv, Vp, NODES, DIM, DIM);

    int ethreads = EDGES * 32;
    edge_attn<<<(ethreads + 255) / 256, 256>>>(send, recv);
    scatter_msg<<<(ethreads + 255) / 256, 256>>>(send, recv);

    sgemm_bias<<<gemmGrid, 256>>>(Ap, Wff, bff, out, NODES, DIM, DIM);
}

// round 3
// speedup vs baseline: 2.0807x; 2.0807x over previous
#include <cuda_runtime.h>
#include <cuda_bf16.h>
#include <cstdint>

#define NODES 25000
#define EDGES 150000
#define DIM   512
#define HEADS 8

// ---------------- scratch (device globals: no runtime allocation) ----------
__device__ __align__(256) float g_K[NODES * DIM];
__device__ __align__(256) float g_Q[NODES * DIM];
__device__ __align__(256) float g_V[NODES * DIM];
__device__ __align__(256) float g_E[EDGES * HEADS];
__device__ __align__(256) float g_S[NODES * HEADS];
__device__ __align__(256) float g_AGG[NODES * DIM];
// bf16 split operands
__device__ __align__(256) __nv_bfloat16 g_XH[NODES * DIM];
__device__ __align__(256) __nv_bfloat16 g_XL[NODES * DIM];
__device__ __align__(256) __nv_bfloat16 g_GH[NODES * DIM];   // split of AGG
__device__ __align__(256) __nv_bfloat16 g_GL[NODES * DIM];
__device__ __align__(256) __nv_bfloat16 g_WTH[4 * DIM * DIM]; // transposed weights [N][K]
__device__ __align__(256) __nv_bfloat16 g_WTL[4 * DIM * DIM];

// =================== helpers ===================
__device__ __forceinline__ uint32_t smem_u32(const void* p) {
    uint32_t a;
    asm("{ .reg .u64 t; cvta.to.shared.u64 t, %1; cvt.u32.u64 %0, t; }"
        : "=r"(a) : "l"(p));
    return a;
}
__device__ __forceinline__ void bf16_split(float v, __nv_bfloat16& h, __nv_bfloat16& l) {
    h = __float2bfloat16_rn(v);
    l = __float2bfloat16_rn(v - __bfloat162float(h));
}

#define CP_ASYNC(dst, src, sz) \
    asm volatile("cp.async.cg.shared.global [%0], [%1], 16, %2;" \
                 :: "r"(dst), "l"(src), "r"(sz) : "memory")
#define CP_COMMIT() asm volatile("cp.async.commit_group;" ::: "memory")

#define LDMATRIX_X4(r0, r1, r2, r3, a) \
    asm volatile("ldmatrix.sync.aligned.m8n8.x4.shared.b16 {%0,%1,%2,%3}, [%4];" \
                 : "=r"(r0), "=r"(r1), "=r"(r2), "=r"(r3) : "r"(a))

#define MMA_BF16(d, a0, a1, a2, a3, b0, b1)                                   \
    asm volatile("mma.sync.aligned.m16n8k16.row.col.f32.bf16.bf16.f32 "       \
                 "{%0,%1,%2,%3}, {%4,%5,%6,%7}, {%8,%9}, {%0,%1,%2,%3};"      \
                 : "+f"((d)[0]), "+f"((d)[1]), "+f"((d)[2]), "+f"((d)[3])     \
                 : "r"(a0), "r"(a1), "r"(a2), "r"(a3), "r"(b0), "r"(b1))

// =================== bf16 3-term split GEMM =================================
// C[M,512] = A[M,512] @ B^T + bias, where A = Ah+Al, B (as BT[N][K]) = Bh+Bl.
// CTA tile 128x128, BK=32, 8 warps (warp tile 64x32), 2-stage cp.async pipe.
#define BM 128
#define BN 128
#define BK 32
#define KCHUNKS (DIM / BK)
#define PITCH 80                      // bytes per smem row (32 bf16 + 8 pad)
#define HALF_SZ (128 * PITCH)         // 10240 bytes: one 128x32 bf16 tile
#define STAGE_SZ (4 * HALF_SZ)        // Ah, Al, Bh, Bl = 40960
#define SMEM_TOTAL (2 * STAGE_SZ)     // 81920

__global__ void __launch_bounds__(256, 1) gemm_bf16x3(
    const __nv_bfloat16* __restrict__ Ah, const __nv_bfloat16* __restrict__ Al,
    const __nv_bfloat16* __restrict__ Bh, const __nv_bfloat16* __restrict__ Bl,
    const float* __restrict__ bias, float* __restrict__ C, int M)
{
    extern __shared__ char smem[];
    const uint32_t sb = smem_u32(smem);
    const int tid = threadIdx.x, wid = tid >> 5, lane = tid & 31;
    const int warpRow = wid & 1, warpCol = wid >> 1;      // 2 x 4 warps
    const int rowBase = blockIdx.y * BM;
    const int nBase = blockIdx.x * BN;

    // per-thread cp.async mapping: 2 chunks of 16B per array per stage
    const int c0 = tid, c1 = tid + 256;
    const int lr0 = c0 >> 2, lk0 = c0 & 3;                // row, 16B-chunk in row
    const int lr1 = c1 >> 2, lk1 = c1 & 3;
    const uint32_t so0 = (uint32_t)(lr0 * PITCH + lk0 * 16);
    const uint32_t so1 = (uint32_t)(lr1 * PITCH + lk1 * 16);
    const uint32_t szA0 = (rowBase + lr0 < M) ? 16u : 0u;
    const uint32_t szA1 = (rowBase + lr1 < M) ? 16u : 0u;
    const size_t gA0 = (size_t)(rowBase + lr0) * DIM + lk0 * 8;
    const size_t gA1 = (size_t)(rowBase + lr1) * DIM + lk1 * 8;
    const size_t gB0 = (size_t)(nBase + lr0) * DIM + lk0 * 8;
    const size_t gB1 = (size_t)(nBase + lr1) * DIM + lk1 * 8;

    // ldmatrix per-thread base offsets
    const uint32_t aOff = (uint32_t)((warpRow * 64 + (lane & 7) + ((lane >> 3) & 1) * 8) * PITCH
                                     + (lane >> 4) * 16);
    const uint32_t bOff = (uint32_t)((warpCol * 32 + (lane >> 4) * 8 + (lane & 7)) * PITCH
                                     + ((lane >> 3) & 1) * 16);

    float acc[4][4][4];
#pragma unroll
    for (int f = 0; f < 4; f++)
#pragma unroll
        for (int g = 0; g < 4; g++)
#pragma unroll
            for (int i = 0; i < 4; i++) acc[f][g][i] = 0.0f;

    auto load_stage = [&](int chunk, int buf) {
        const int k0 = chunk * BK;
        const uint32_t st = sb + (uint32_t)buf * STAGE_SZ;
        CP_ASYNC(st + so0,                 Ah + gA0 + k0, szA0);
        CP_ASYNC(st + so1,                 Ah + gA1 + k0, szA1);
        CP_ASYNC(st + HALF_SZ + so0,       Al + gA0 + k0, szA0);
        CP_ASYNC(st + HALF_SZ + so1,       Al + gA1 + k0, szA1);
        CP_ASYNC(st + 2 * HALF_SZ + so0,   Bh + gB0 + k0, 16u);
        CP_ASYNC(st + 2 * HALF_SZ + so1,   Bh + gB1 + k0, 16u);
        CP_ASYNC(st + 3 * HALF_SZ + so0,   Bl + gB0 + k0, 16u);
        CP_ASYNC(st + 3 * HALF_SZ + so1,   Bl + gB1 + k0, 16u);
        CP_COMMIT();
    };

    load_stage(0, 0);

    for (int c = 0; c < KCHUNKS; c++) {
        if (c + 1 < KCHUNKS) {
            load_stage(c + 1, (c + 1) & 1);
            asm volatile("cp.async.wait_group 1;" ::: "memory");
        } else {
            asm volatile("cp.async.wait_group 0;" ::: "memory");
        }
        __syncthreads();

        const uint32_t st = sb + (uint32_t)(c & 1) * STAGE_SZ;
#pragma unroll
        for (int ks = 0; ks < 2; ks++) {
            const uint32_t kb = (uint32_t)(ks * 32);
            uint32_t aH[4][4], aL[4][4], bH[4][2], bL[4][2];
#pragma unroll
            for (int f = 0; f < 4; f++) {
                LDMATRIX_X4(aH[f][0], aH[f][1], aH[f][2], aH[f][3],
                            st + aOff + (uint32_t)(f * 16 * PITCH) + kb);
                LDMATRIX_X4(aL[f][0], aL[f][1], aL[f][2], aL[f][3],
                            st + HALF_SZ + aOff + (uint32_t)(f * 16 * PITCH) + kb);
            }
#pragma unroll
            for (int p = 0; p < 2; p++) {
                LDMATRIX_X4(bH[2 * p][0], bH[2 * p][1], bH[2 * p + 1][0], bH[2 * p + 1][1],
                            st + 2 * HALF_SZ + bOff + (uint32_t)(p * 16 * PITCH) + kb);
                LDMATRIX_X4(bL[2 * p][0], bL[2 * p][1], bL[2 * p + 1][0], bL[2 * p + 1][1],
                            st + 3 * HALF_SZ + bOff + (uint32_t)(p * 16 * PITCH) + kb);
            }
#pragma unroll
            for (int f = 0; f < 4; f++)
#pragma unroll
                for (int g = 0; g < 4; g++) {
                    MMA_BF16(acc[f][g], aH[f][0], aH[f][1], aH[f][2], aH[f][3],
                             bH[g][0], bH[g][1]);
                    MMA_BF16(acc[f][g], aH[f][0], aH[f][1], aH[f][2], aH[f][3],
                             bL[g][0], bL[g][1]);
                    MMA_BF16(acc[f][g], aL[f][0], aL[f][1], aL[f][2], aL[f][3],
                             bH[g][0], bH[g][1]);
                }
        }
        __syncthreads();
    }

    // ---- epilogue ----
#pragma unroll
    for (int f = 0; f < 4; f++) {
        const int r0 = rowBase + warpRow * 64 + f * 16 + (lane >> 2);
#pragma unroll
        for (int g = 0; g < 4; g++) {
            const int col = nBase + warpCol * 32 + g * 8 + (lane & 3) * 2;
            const float2 b = *(const float2*)(bias + col);
            if (r0 < M) {
                float2 o = make_float2(acc[f][g][0] + b.x, acc[f][g][1] + b.y);
                *(float2*)(C + (size_t)r0 * DIM + col) = o;
            }
            if (r0 + 8 < M) {
                float2 o = make_float2(acc[f][g][2] + b.x, acc[f][g][3] + b.y);
                *(float2*)(C + (size_t)(r0 + 8) * DIM + col) = o;
            }
        }
    }
}

// =================== weight transpose + bf16 split (512x512) ===============
__global__ void transpose_split(const float* __restrict__ in,
                                __nv_bfloat16* __restrict__ oh,
                                __nv_bfloat16* __restrict__ ol) {
    __shared__ float t[32][33];
    int bx = blockIdx.x * 32, by = blockIdx.y * 32;
    int x = bx + threadIdx.x;
#pragma unroll
    for (int j = 0; j < 32; j += 8)
        t[threadIdx.y + j][threadIdx.x] = in[(size_t)(by + threadIdx.y + j) * DIM + x];
    __syncthreads();
    int x2 = by + threadIdx.x;
#pragma unroll
    for (int j = 0; j < 32; j += 8) {
        float v = t[threadIdx.x][threadIdx.y + j];
        __nv_bfloat16 h, l; bf16_split(v, h, l);
        size_t o = (size_t)(bx + threadIdx.y + j) * DIM + x2;
        oh[o] = h; ol[o] = l;
    }
}

// =================== fp32 -> bf16 hi/lo split ===============================
__global__ void split_arr(const float* __restrict__ in,
                          __nv_bfloat16* __restrict__ oh,
                          __nv_bfloat16* __restrict__ ol, int n4) {
    int i = blockIdx.x * blockDim.x + threadIdx.x;
    if (i >= n4) return;
    float4 v = ((const float4*)in)[i];
    __nv_bfloat16 h0, l0, h1, l1, h2, l2, h3, l3;
    bf16_split(v.x, h0, l0); bf16_split(v.y, h1, l1);
    bf16_split(v.z, h2, l2); bf16_split(v.w, h3, l3);
    __nv_bfloat162 hA{h0, h1}, hB{h2, h3}, lA{l0, l1}, lB{l2, l3};
    ((__nv_bfloat162*)oh)[2 * i] = hA; ((__nv_bfloat162*)oh)[2 * i + 1] = hB;
    ((__nv_bfloat162*)ol)[2 * i] = lA; ((__nv_bfloat162*)ol)[2 * i + 1] = lB;
}

// =================== zero scratch ===================
__global__ void zero_scratch() {
    int i = blockIdx.x * blockDim.x + threadIdx.x;
    if (i < NODES * DIM)   g_AGG[i] = 0.0f;
    if (i < NODES * HEADS) g_S[i]   = 0.0f;
}

// =================== edge scores: warp per edge ===================
__global__ void edge_attn(const int* __restrict__ send,
                          const int* __restrict__ recv)
{
    int g = blockIdx.x * blockDim.x + threadIdx.x;
    int m = g >> 5;
    if (m >= EDGES) return;
    int lane = g & 31;
    int h = lane >> 2, part = lane & 3;
    int s = send[m], r = recv[m];

    const float4* q = (const float4*)&g_Q[(size_t)r * DIM + h * 64 + part * 16];
    const float4* k = (const float4*)&g_K[(size_t)s * DIM + h * 64 + part * 16];
    float acc = 0.0f;
#pragma unroll
    for (int i = 0; i < 4; i++) {
        float4 a = q[i], b = k[i];
        acc += a.x * b.x + a.y * b.y + a.z * b.z + a.w * b.w;
    }
    acc += __shfl_xor_sync(0xffffffffu, acc, 1);
    acc += __shfl_xor_sync(0xffffffffu, acc, 2);
    if (part == 0) {
        float e = __expf(acc * 0.125f);
        g_E[m * HEADS + h] = e;
        atomicAdd(&g_S[r * HEADS + h], e);
    }
}

// =================== weighted message scatter-add ===================
__global__ void scatter_msg(const int* __restrict__ send,
                            const int* __restrict__ recv)
{
    int g = blockIdx.x * blockDim.x + threadIdx.x;
    int m = g >> 5;
    if (m >= EDGES) return;
    int lane = g & 31;
    int h = lane >> 2, part = lane & 3;
    int s = send[m], r = recv[m];

    float w = g_E[m * HEADS + h] / g_S[r * HEADS + h];

    const float4* v = (const float4*)&g_V[(size_t)s * DIM + h * 64 + part * 16];
    float* dst = &g_AGG[(size_t)r * DIM + h * 64 + part * 16];
#pragma unroll
    for (int i = 0; i < 4; i++) {
        float4 mv = v[i];
        mv.x *= w; mv.y *= w; mv.z *= w; mv.w *= w;
        asm volatile("red.global.add.v4.f32 [%0], {%1, %2, %3, %4};"
                     :: "l"(dst + i * 4),
                        "f"(mv.x), "f"(mv.y), "f"(mv.z), "f"(mv.w)
                     : "memory");
    }
}

// ---------------------------------------------------------------------------
extern "C" void kernel_launch(void* const* d_in, const int* in_sizes, int n_in,
                              void* d_out, int out_size) {
    const float* x   = (const float*)d_in[0];
    const int*  eidx = (const int*)  d_in[1];
    const float* Wk  = (const float*)d_in[2];
    const float* bk  = (const float*)d_in[3];
    const float* Wq  = (const float*)d_in[4];
    const float* bq  = (const float*)d_in[5];
    const float* Wv  = (const float*)d_in[6];
    const float* bv  = (const float*)d_in[7];
    const float* Wff = (const float*)d_in[8];
    const float* bff = (const float*)d_in[9];
    float* out = (float*)d_out;

    const int* send = eidx;
    const int* recv = eidx + EDGES;

    float *Kp, *Qp, *Vp, *Ap;
    __nv_bfloat16 *XH, *XL, *GH, *GL, *WTH, *WTL;
    cudaGetSymbolAddress((void**)&Kp,  g_K);
    cudaGetSymbolAddress((void**)&Qp,  g_Q);
    cudaGetSymbolAddress((void**)&Vp,  g_V);
    cudaGetSymbolAddress((void**)&Ap,  g_AGG);
    cudaGetSymbolAddress((void**)&XH,  g_XH);
    cudaGetSymbolAddress((void**)&XL,  g_XL);
    cudaGetSymbolAddress((void**)&GH,  g_GH);
    cudaGetSymbolAddress((void**)&GL,  g_GL);
    cudaGetSymbolAddress((void**)&WTH, g_WTH);
    cudaGetSymbolAddress((void**)&WTL, g_WTL);

    cudaFuncSetAttribute(gemm_bf16x3,
        cudaFuncAttributeMaxDynamicSharedMemorySize, SMEM_TOTAL);

    dim3 tgrid(16, 16), tblk(32, 8);
    transpose_split<<<tgrid, tblk>>>(Wk,  WTH + 0 * DIM * DIM, WTL + 0 * DIM * DIM);
    transpose_split<<<tgrid, tblk>>>(Wq,  WTH + 1 * DIM * DIM, WTL + 1 * DIM * DIM);
    transpose_split<<<tgrid, tblk>>>(Wv,  WTH + 2 * DIM * DIM, WTL + 2 * DIM * DIM);
    transpose_split<<<tgrid, tblk>>>(Wff, WTH + 3 * DIM * DIM, WTL + 3 * DIM * DIM);

    const int n4 = NODES * DIM / 4;
    split_arr<<<(n4 + 255) / 256, 256>>>(x, XH, XL, n4);
    zero_scratch<<<(NODES * DIM + 255) / 256, 256>>>();

    dim3 ggrid(DIM / BN, (NODES + BM - 1) / BM);   // (4, 196)
    gemm_bf16x3<<<ggrid, 256, SMEM_TOTAL>>>(XH, XL, WTH + 0 * DIM * DIM,
                                            WTL + 0 * DIM * DIM, bk, Kp, NODES);
    gemm_bf16x3<<<ggrid, 256, SMEM_TOTAL>>>(XH, XL, WTH + 1 * DIM * DIM,
                                            WTL + 1 * DIM * DIM, bq, Qp, NODES);
    gemm_bf16x3<<<ggrid, 256, SMEM_TOTAL>>>(XH, XL, WTH + 2 * DIM * DIM,
                                            WTL + 2 * DIM * DIM, bv, Vp, NODES);

    int ethreads = EDGES * 32;
    edge_attn<<<(ethreads + 255) / 256, 256>>>(send, recv);
    scatter_msg<<<(ethreads + 255) / 256, 256>>>(send, recv);

    split_arr<<<(n4 + 255) / 256, 256>>>(Ap, GH, GL, n4);
    gemm_bf16x3<<<ggrid, 256, SMEM_TOTAL>>>(GH, GL, WTH + 3 * DIM * DIM,
                                            WTL + 3 * DIM * DIM, bff, out, NODES);
}

// round 4
// speedup vs baseline: 2.5034x; 1.2032x over previous
#include <cuda_runtime.h>
#include <cuda_bf16.h>
#include <cstdint>

#define NODES 25000
#define EDGES 150000
#define DIM   512
#define NKQV  1536
#define HEADS 8

// ---------------- scratch (device globals) ----------------
__device__ __align__(256) float g_KQV[NODES * NKQV];          // [node][K|Q|V]
__device__ __align__(256) __nv_bfloat16 g_XH[NODES * DIM];
__device__ __align__(256) __nv_bfloat16 g_XL[NODES * DIM];
__device__ __align__(256) __nv_bfloat16 g_GH[NODES * DIM];    // agg hi
__device__ __align__(256) __nv_bfloat16 g_GL[NODES * DIM];    // agg lo
__device__ __align__(256) __nv_bfloat16 g_WTH[4 * DIM * DIM]; // W^T hi [N][K]
__device__ __align__(256) __nv_bfloat16 g_WTL[4 * DIM * DIM];
__device__ __align__(256) float g_bias[NKQV];
// CSR
__device__ int g_cnt[NODES + 1];
__device__ int g_fill[NODES];
__device__ int g_esend[EDGES];

// =================== helpers ===================
__device__ __forceinline__ uint32_t smem_u32(const void* p) {
    uint32_t a;
    asm("{ .reg .u64 t; cvta.to.shared.u64 t, %1; cvt.u32.u64 %0, t; }"
        : "=r"(a) : "l"(p));
    return a;
}
__device__ __forceinline__ void bf16_split(float v, __nv_bfloat16& h, __nv_bfloat16& l) {
    h = __float2bfloat16_rn(v);
    l = __float2bfloat16_rn(v - __bfloat162float(h));
}

#define CP_ASYNC(dst, src, sz) \
    asm volatile("cp.async.cg.shared.global [%0], [%1], 16, %2;" \
                 :: "r"(dst), "l"(src), "r"(sz) : "memory")
#define CP_COMMIT() asm volatile("cp.async.commit_group;" ::: "memory")

#define LDMATRIX_X4(r0, r1, r2, r3, a) \
    asm volatile("ldmatrix.sync.aligned.m8n8.x4.shared.b16 {%0,%1,%2,%3}, [%4];" \
                 : "=r"(r0), "=r"(r1), "=r"(r2), "=r"(r3) : "r"(a))

#define MMA_BF16(d, a0, a1, a2, a3, b0, b1)                                   \
    asm volatile("mma.sync.aligned.m16n8k16.row.col.f32.bf16.bf16.f32 "       \
                 "{%0,%1,%2,%3}, {%4,%5,%6,%7}, {%8,%9}, {%0,%1,%2,%3};"      \
                 : "+f"((d)[0]), "+f"((d)[1]), "+f"((d)[2]), "+f"((d)[3])     \
                 : "r"(a0), "r"(a1), "r"(a2), "r"(a3), "r"(b0), "r"(b1))

// =================== bf16 3-term split GEMM =================================
// C[M,N] = A[M,512] @ BT^T + bias (BT: [N][512] row-major). CTA 128x128, BK=32.
#define BM 128
#define BN 128
#define BK 32
#define KCHUNKS (DIM / BK)
#define PITCH 80
#define HALF_SZ (128 * PITCH)
#define STAGE_SZ (4 * HALF_SZ)
#define SMEM_TOTAL (2 * STAGE_SZ)

__global__ void __launch_bounds__(256, 1) gemm_bf16x3(
    const __nv_bfloat16* __restrict__ Ah, const __nv_bfloat16* __restrict__ Al,
    const __nv_bfloat16* __restrict__ Bh, const __nv_bfloat16* __restrict__ Bl,
    const float* __restrict__ bias, float* __restrict__ C, int M, int ldc)
{
    extern __shared__ char smem[];
    const uint32_t sb = smem_u32(smem);
    const int tid = threadIdx.x, wid = tid >> 5, lane = tid & 31;
    const int warpRow = wid & 1, warpCol = wid >> 1;
    const int rowBase = blockIdx.y * BM;
    const int nBase = blockIdx.x * BN;

    const int c0 = tid, c1 = tid + 256;
    const int lr0 = c0 >> 2, lk0 = c0 & 3;
    const int lr1 = c1 >> 2, lk1 = c1 & 3;
    const uint32_t so0 = (uint32_t)(lr0 * PITCH + lk0 * 16);
    const uint32_t so1 = (uint32_t)(lr1 * PITCH + lk1 * 16);
    const uint32_t szA0 = (rowBase + lr0 < M) ? 16u : 0u;
    const uint32_t szA1 = (rowBase + lr1 < M) ? 16u : 0u;
    const size_t gA0 = (size_t)(rowBase + lr0) * DIM + lk0 * 8;
    const size_t gA1 = (size_t)(rowBase + lr1) * DIM + lk1 * 8;
    const size_t gB0 = (size_t)(nBase + lr0) * DIM + lk0 * 8;
    const size_t gB1 = (size_t)(nBase + lr1) * DIM + lk1 * 8;

    const uint32_t aOff = (uint32_t)((warpRow * 64 + (lane & 7) + ((lane >> 3) & 1) * 8) * PITCH
                                     + (lane >> 4) * 16);
    const uint32_t bOff = (uint32_t)((warpCol * 32 + (lane >> 4) * 8 + (lane & 7)) * PITCH
                                     + ((lane >> 3) & 1) * 16);

    float acc[4][4][4];
#pragma unroll
    for (int f = 0; f < 4; f++)
#pragma unroll
        for (int g = 0; g < 4; g++)
#pragma unroll
            for (int i = 0; i < 4; i++) acc[f][g][i] = 0.0f;

    auto load_stage = [&](int chunk, int buf) {
        const int k0 = chunk * BK;
        const uint32_t st = sb + (uint32_t)buf * STAGE_SZ;
        CP_ASYNC(st + so0,               Ah + gA0 + k0, szA0);
        CP_ASYNC(st + so1,               Ah + gA1 + k0, szA1);
        CP_ASYNC(st + HALF_SZ + so0,     Al + gA0 + k0, szA0);
        CP_ASYNC(st + HALF_SZ + so1,     Al + gA1 + k0, szA1);
        CP_ASYNC(st + 2 * HALF_SZ + so0, Bh + gB0 + k0, 16u);
        CP_ASYNC(st + 2 * HALF_SZ + so1, Bh + gB1 + k0, 16u);
        CP_ASYNC(st + 3 * HALF_SZ + so0, Bl + gB0 + k0, 16u);
        CP_ASYNC(st + 3 * HALF_SZ + so1, Bl + gB1 + k0, 16u);
        CP_COMMIT();
    };

    load_stage(0, 0);

    for (int c = 0; c < KCHUNKS; c++) {
        if (c + 1 < KCHUNKS) {
            load_stage(c + 1, (c + 1) & 1);
            asm volatile("cp.async.wait_group 1;" ::: "memory");
        } else {
            asm volatile("cp.async.wait_group 0;" ::: "memory");
        }
        __syncthreads();

        const uint32_t st = sb + (uint32_t)(c & 1) * STAGE_SZ;
#pragma unroll
        for (int ks = 0; ks < 2; ks++) {
            const uint32_t kb = (uint32_t)(ks * 32);
            uint32_t aH[4][4], aL[4][4], bH[4][2], bL[4][2];
#pragma unroll
            for (int f = 0; f < 4; f++) {
                LDMATRIX_X4(aH[f][0], aH[f][1], aH[f][2], aH[f][3],
                            st + aOff + (uint32_t)(f * 16 * PITCH) + kb);
                LDMATRIX_X4(aL[f][0], aL[f][1], aL[f][2], aL[f][3],
                            st + HALF_SZ + aOff + (uint32_t)(f * 16 * PITCH) + kb);
            }
#pragma unroll
            for (int p = 0; p < 2; p++) {
                LDMATRIX_X4(bH[2 * p][0], bH[2 * p][1], bH[2 * p + 1][0], bH[2 * p + 1][1],
                            st + 2 * HALF_SZ + bOff + (uint32_t)(p * 16 * PITCH) + kb);
                LDMATRIX_X4(bL[2 * p][0], bL[2 * p][1], bL[2 * p + 1][0], bL[2 * p + 1][1],
                            st + 3 * HALF_SZ + bOff + (uint32_t)(p * 16 * PITCH) + kb);
            }
#pragma unroll
            for (int f = 0; f < 4; f++)
#pragma unroll
                for (int g = 0; g < 4; g++) {
                    MMA_BF16(acc[f][g], aH[f][0], aH[f][1], aH[f][2], aH[f][3],
                             bH[g][0], bH[g][1]);
                    MMA_BF16(acc[f][g], aH[f][0], aH[f][1], aH[f][2], aH[f][3],
                             bL[g][0], bL[g][1]);
                    MMA_BF16(acc[f][g], aL[f][0], aL[f][1], aL[f][2], aL[f][3],
                             bH[g][0], bH[g][1]);
                }
        }
        __syncthreads();
    }

#pragma unroll
    for (int f = 0; f < 4; f++) {
        const int r0 = rowBase + warpRow * 64 + f * 16 + (lane >> 2);
#pragma unroll
        for (int g = 0; g < 4; g++) {
            const int col = nBase + warpCol * 32 + g * 8 + (lane & 3) * 2;
            const float2 b = *(const float2*)(bias + col);
            if (r0 < M) {
                float2 o = make_float2(acc[f][g][0] + b.x, acc[f][g][1] + b.y);
                *(float2*)(C + (size_t)r0 * ldc + col) = o;
            }
            if (r0 + 8 < M) {
                float2 o = make_float2(acc[f][g][2] + b.x, acc[f][g][3] + b.y);
                *(float2*)(C + (size_t)(r0 + 8) * ldc + col) = o;
            }
        }
    }
}

// =================== weight transpose + bf16 split ===================
__global__ void transpose_split(const float* __restrict__ in,
                                __nv_bfloat16* __restrict__ oh,
                                __nv_bfloat16* __restrict__ ol) {
    __shared__ float t[32][33];
    int bx = blockIdx.x * 32, by = blockIdx.y * 32;
    int x = bx + threadIdx.x;
#pragma unroll
    for (int j = 0; j < 32; j += 8)
        t[threadIdx.y + j][threadIdx.x] = in[(size_t)(by + threadIdx.y + j) * DIM + x];
    __syncthreads();
    int x2 = by + threadIdx.x;
#pragma unroll
    for (int j = 0; j < 32; j += 8) {
        float v = t[threadIdx.x][threadIdx.y + j];
        __nv_bfloat16 h, l; bf16_split(v, h, l);
        size_t o = (size_t)(bx + threadIdx.y + j) * DIM + x2;
        oh[o] = h; ol[o] = l;
    }
}

// =================== fp32 -> bf16 hi/lo split ===================
__global__ void split_arr(const float* __restrict__ in,
                          __nv_bfloat16* __restrict__ oh,
                          __nv_bfloat16* __restrict__ ol, int n4) {
    int i = blockIdx.x * blockDim.x + threadIdx.x;
    if (i >= n4) return;
    float4 v = ((const float4*)in)[i];
    __nv_bfloat16 h0, l0, h1, l1, h2, l2, h3, l3;
    bf16_split(v.x, h0, l0); bf16_split(v.y, h1, l1);
    bf16_split(v.z, h2, l2); bf16_split(v.w, h3, l3);
    __nv_bfloat162 hA{h0, h1}, hB{h2, h3}, lA{l0, l1}, lB{l2, l3};
    ((__nv_bfloat162*)oh)[2 * i] = hA; ((__nv_bfloat162*)oh)[2 * i + 1] = hB;
    ((__nv_bfloat162*)ol)[2 * i] = lA; ((__nv_bfloat162*)ol)[2 * i + 1] = lB;
}

// =================== bias concat ===================
__global__ void concat_bias(const float* __restrict__ bk,
                            const float* __restrict__ bq,
                            const float* __restrict__ bv) {
    int i = blockIdx.x * blockDim.x + threadIdx.x;
    if (i < DIM) {
        g_bias[i] = bk[i];
        g_bias[DIM + i] = bq[i];
        g_bias[2 * DIM + i] = bv[i];
    }
}

// =================== CSR build ===================
__global__ void zero_csr() {
    int i = blockIdx.x * blockDim.x + threadIdx.x;
    if (i <= NODES) g_cnt[i] = 0;
    if (i < NODES)  g_fill[i] = 0;
}
__global__ void hist_recv(const int* __restrict__ recv) {
    int e = blockIdx.x * blockDim.x + threadIdx.x;
    if (e < EDGES) atomicAdd(&g_cnt[recv[e] + 1], 1);
}
#define SCAN_T 1024
#define SCHUNK 25   // 1024*25 = 25600 >= 25001
__global__ void __launch_bounds__(SCAN_T) scan_offsets() {
    __shared__ int sums[SCAN_T];
    int t = threadIdx.x;
    int base = t * SCHUNK;
    int vals[SCHUNK];
    int s = 0;
#pragma unroll
    for (int i = 0; i < SCHUNK; i++) {
        int idx = base + i;
        vals[i] = (idx <= NODES) ? g_cnt[idx] : 0;
        s += vals[i];
    }
    sums[t] = s;
    __syncthreads();
    for (int d = 1; d < SCAN_T; d <<= 1) {
        int v = (t >= d) ? sums[t - d] : 0;
        __syncthreads();
        sums[t] += v;
        __syncthreads();
    }
    int run = (t > 0) ? sums[t - 1] : 0;
#pragma unroll
    for (int i = 0; i < SCHUNK; i++) {
        run += vals[i];
        int idx = base + i;
        if (idx <= NODES) g_cnt[idx] = run;
    }
}
__global__ void scatter_csr(const int* __restrict__ send,
                            const int* __restrict__ recv) {
    int e = blockIdx.x * blockDim.x + threadIdx.x;
    if (e >= EDGES) return;
    int r = recv[e];
    int pos = g_cnt[r] + atomicAdd(&g_fill[r], 1);
    g_esend[pos] = send[e];
}

// =================== fused node attention + aggregation =====================
// Warp per node: softmax over incoming edges + weighted V aggregation,
// writes bf16 hi/lo split of the result directly.
__global__ void __launch_bounds__(256) node_attn_agg() {
    int gw = (blockIdx.x * blockDim.x + threadIdx.x) >> 5;
    if (gw >= NODES) return;
    const int lane = threadIdx.x & 31;
    const int r = gw;

    const float4* qp = (const float4*)&g_KQV[(size_t)r * NKQV + DIM + lane * 16];
    float4 q0 = qp[0], q1 = qp[1], q2 = qp[2], q3 = qp[3];

    const int beg = g_cnt[r], end = g_cnt[r + 1];
    float denom = 0.0f;
    float4 a0 = {0, 0, 0, 0}, a1 = {0, 0, 0, 0}, a2 = {0, 0, 0, 0}, a3 = {0, 0, 0, 0};

    for (int j = beg; j < end; j++) {
        int s = g_esend[j];
        const float4* kp = (const float4*)&g_KQV[(size_t)s * NKQV + lane * 16];
        const float4* vp = (const float4*)&g_KQV[(size_t)s * NKQV + 2 * DIM + lane * 16];
        float4 k0 = kp[0], k1 = kp[1], k2 = kp[2], k3 = kp[3];
        float4 v0 = vp[0], v1 = vp[1], v2 = vp[2], v3 = vp[3];
        float d = q0.x * k0.x + q0.y * k0.y + q0.z * k0.z + q0.w * k0.w
                + q1.x * k1.x + q1.y * k1.y + q1.z * k1.z + q1.w * k1.w
                + q2.x * k2.x + q2.y * k2.y + q2.z * k2.z + q2.w * k2.w
                + q3.x * k3.x + q3.y * k3.y + q3.z * k3.z + q3.w * k3.w;
        d += __shfl_xor_sync(0xffffffffu, d, 1);
        d += __shfl_xor_sync(0xffffffffu, d, 2);
        float w = __expf(d * 0.125f);
        denom += w;
        a0.x += w * v0.x; a0.y += w * v0.y; a0.z += w * v0.z; a0.w += w * v0.w;
        a1.x += w * v1.x; a1.y += w * v1.y; a1.z += w * v1.z; a1.w += w * v1.w;
        a2.x += w * v2.x; a2.y += w * v2.y; a2.z += w * v2.z; a2.w += w * v2.w;
        a3.x += w * v3.x; a3.y += w * v3.y; a3.z += w * v3.z; a3.w += w * v3.w;
    }

    float inv = (denom > 0.0f) ? 1.0f / denom : 0.0f;
    float vals[16] = {a0.x * inv, a0.y * inv, a0.z * inv, a0.w * inv,
                      a1.x * inv, a1.y * inv, a1.z * inv, a1.w * inv,
                      a2.x * inv, a2.y * inv, a2.z * inv, a2.w * inv,
                      a3.x * inv, a3.y * inv, a3.z * inv, a3.w * inv};
    __nv_bfloat162 hp[8], lp[8];
#pragma unroll
    for (int i = 0; i < 8; i++) {
        __nv_bfloat16 h0, l0, h1, l1;
        bf16_split(vals[2 * i], h0, l0);
        bf16_split(vals[2 * i + 1], h1, l1);
        hp[i] = __nv_bfloat162{h0, h1};
        lp[i] = __nv_bfloat162{l0, l1};
    }
    uint4* dh = (uint4*)&g_GH[(size_t)r * DIM + lane * 16];
    uint4* dl = (uint4*)&g_GL[(size_t)r * DIM + lane * 16];
    dh[0] = ((const uint4*)hp)[0];
    dh[1] = ((const uint4*)hp)[1];
    dl[0] = ((const uint4*)lp)[0];
    dl[1] = ((const uint4*)lp)[1];
}

// ---------------------------------------------------------------------------
extern "C" void kernel_launch(void* const* d_in, const int* in_sizes, int n_in,
                              void* d_out, int out_size) {
    const float* x   = (const float*)d_in[0];
    const int*  eidx = (const int*)  d_in[1];
    const float* Wk  = (const float*)d_in[2];
    const float* bk  = (const float*)d_in[3];
    const float* Wq  = (const float*)d_in[4];
    const float* bq  = (const float*)d_in[5];
    const float* Wv  = (const float*)d_in[6];
    const float* bv  = (const float*)d_in[7];
    const float* Wff = (const float*)d_in[8];
    const float* bff = (const float*)d_in[9];
    float* out = (float*)d_out;

    const int* send = eidx;
    const int* recv = eidx + EDGES;

    float *KQVp, *biasp;
    __nv_bfloat16 *XH, *XL, *GH, *GL, *WTH, *WTL;
    cudaGetSymbolAddress((void**)&KQVp, g_KQV);
    cudaGetSymbolAddress((void**)&biasp, g_bias);
    cudaGetSymbolAddress((void**)&XH,  g_XH);
    cudaGetSymbolAddress((void**)&XL,  g_XL);
    cudaGetSymbolAddress((void**)&GH,  g_GH);
    cudaGetSymbolAddress((void**)&GL,  g_GL);
    cudaGetSymbolAddress((void**)&WTH, g_WTH);
    cudaGetSymbolAddress((void**)&WTL, g_WTL);

    cudaFuncSetAttribute(gemm_bf16x3,
        cudaFuncAttributeMaxDynamicSharedMemorySize, SMEM_TOTAL);

    // ---- prep: weights (K|Q|V order matches g_KQV columns), x split, bias
    dim3 tgrid(16, 16), tblk(32, 8);
    transpose_split<<<tgrid, tblk>>>(Wk,  WTH + 0 * DIM * DIM, WTL + 0 * DIM * DIM);
    transpose_split<<<tgrid, tblk>>>(Wq,  WTH + 1 * DIM * DIM, WTL + 1 * DIM * DIM);
    transpose_split<<<tgrid, tblk>>>(Wv,  WTH + 2 * DIM * DIM, WTL + 2 * DIM * DIM);
    transpose_split<<<tgrid, tblk>>>(Wff, WTH + 3 * DIM * DIM, WTL + 3 * DIM * DIM);
    concat_bias<<<2, 256>>>(bk, bq, bv);

    const int n4 = NODES * DIM / 4;
    split_arr<<<(n4 + 255) / 256, 256>>>(x, XH, XL, n4);

    // ---- CSR build
    zero_csr<<<(NODES + 256) / 256, 256>>>();
    hist_recv<<<(EDGES + 255) / 256, 256>>>(recv);
    scan_offsets<<<1, SCAN_T>>>();
    scatter_csr<<<(EDGES + 255) / 256, 256>>>(send, recv);

    // ---- fused K|Q|V GEMM: [25000 x 1536]
    dim3 gkqv(NKQV / BN, (NODES + BM - 1) / BM);   // (12, 196)
    gemm_bf16x3<<<gkqv, 256, SMEM_TOTAL>>>(XH, XL, WTH, WTL, biasp,
                                           KQVp, NODES, NKQV);

    // ---- fused attention + aggregation (writes bf16 split directly)
    node_attn_agg<<<(NODES * 32 + 255) / 256, 256>>>();

    // ---- FF GEMM -> out
    dim3 gff(DIM / BN, (NODES + BM - 1) / BM);     // (4, 196)
    gemm_bf16x3<<<gff, 256, SMEM_TOTAL>>>(GH, GL, WTH + 3 * DIM * DIM,
                                          WTL + 3 * DIM * DIM, bff, out,
                                          NODES, DIM);
}

// round 5
// speedup vs baseline: 2.6716x; 1.0672x over previous
#include <cuda_runtime.h>
#include <cuda_bf16.h>
#include <cstdint>

#define NODES 25000
#define EDGES 150000
#define DIM   512
#define NKQV  1536
#define HEADS 8

// ---------------- scratch (device globals) ----------------
__device__ __align__(256) float g_KQV[NODES * NKQV];          // [node][K|Q|V]
__device__ __align__(256) __nv_bfloat16 g_XH[NODES * DIM];
__device__ __align__(256) __nv_bfloat16 g_XL[NODES * DIM];
__device__ __align__(256) __nv_bfloat16 g_GH[NODES * DIM];    // agg hi
__device__ __align__(256) __nv_bfloat16 g_GL[NODES * DIM];    // agg lo
__device__ __align__(256) __nv_bfloat16 g_WTH[4 * DIM * DIM]; // W^T hi [N][K]
__device__ __align__(256) __nv_bfloat16 g_WTL[4 * DIM * DIM];
__device__ __align__(256) float g_bias[NKQV];
// CSR
__device__ int g_cnt[NODES + 1];
__device__ int g_fill[NODES];
__device__ int g_esend[EDGES];

// =================== helpers ===================
__device__ __forceinline__ uint32_t smem_u32(const void* p) {
    uint32_t a;
    asm("{ .reg .u64 t; cvta.to.shared.u64 t, %1; cvt.u32.u64 %0, t; }"
        : "=r"(a) : "l"(p));
    return a;
}
__device__ __forceinline__ void bf16_split(float v, __nv_bfloat16& h, __nv_bfloat16& l) {
    h = __float2bfloat16_rn(v);
    l = __float2bfloat16_rn(v - __bfloat162float(h));
}

#define CP_ASYNC(dst, src, sz) \
    asm volatile("cp.async.cg.shared.global [%0], [%1], 16, %2;" \
                 :: "r"(dst), "l"(src), "r"(sz) : "memory")
#define CP_COMMIT() asm volatile("cp.async.commit_group;" ::: "memory")

#define LDMATRIX_X4(r0, r1, r2, r3, a) \
    asm volatile("ldmatrix.sync.aligned.m8n8.x4.shared.b16 {%0,%1,%2,%3}, [%4];" \
                 : "=r"(r0), "=r"(r1), "=r"(r2), "=r"(r3) : "r"(a))

#define MMA_BF16(d, a0, a1, a2, a3, b0, b1)                                   \
    asm volatile("mma.sync.aligned.m16n8k16.row.col.f32.bf16.bf16.f32 "       \
                 "{%0,%1,%2,%3}, {%4,%5,%6,%7}, {%8,%9}, {%0,%1,%2,%3};"      \
                 : "+f"((d)[0]), "+f"((d)[1]), "+f"((d)[2]), "+f"((d)[3])     \
                 : "r"(a0), "r"(a1), "r"(a2), "r"(a3), "r"(b0), "r"(b1))

// =================== bf16 3-term split GEMM =================================
// C[M,N] = A[M,512] @ BT^T + bias (BT: [N][512] row-major).
// CTA tile 128x256, 8 warps (2x4), warp tile 64x64, BK=32, 3-stage cp.async.
#define BM 128
#define BN 256
#define BK 32
#define KCHUNKS (DIM / BK)
#define PITCH 80                       // 32 bf16 + 8 pad bytes per smem row
#define SZ_AT (128 * PITCH)            // 10240: one 128x32 bf16 tile
#define SZ_BT (256 * PITCH)            // 20480: one 256x32 bf16 tile
#define STAGE_SZ (2 * SZ_AT + 2 * SZ_BT)   // Ah, Al, Bh, Bl = 61440
#define NSTAGE 3
#define SMEM_TOTAL (NSTAGE * STAGE_SZ)     // 184320

__global__ void __launch_bounds__(256, 1) gemm_bf16x3(
    const __nv_bfloat16* __restrict__ Ah, const __nv_bfloat16* __restrict__ Al,
    const __nv_bfloat16* __restrict__ Bh, const __nv_bfloat16* __restrict__ Bl,
    const float* __restrict__ bias, float* __restrict__ C, int M, int ldc)
{
    extern __shared__ char smem[];
    const uint32_t sb = smem_u32(smem);
    const int tid = threadIdx.x, wid = tid >> 5, lane = tid & 31;
    const int warpRow = wid & 1, warpCol = wid >> 1;      // 2 x 4
    const int rowBase = blockIdx.y * BM;
    const int nBase = blockIdx.x * BN;

    // A: 512 16B-chunks/half -> 2 per thread. B: 1024 -> 4 per thread.
    const int ar0 = tid >> 1,          ak0 = (tid & 1) * 2;      // rows 0..127, chunk 0/2
    // reuse as two chunks: (ar0, ak0) and (ar0, ak0+1)
    const uint32_t soA0 = (uint32_t)(ar0 * PITCH + ak0 * 16);
    const uint32_t soA1 = soA0 + 16;
    const uint32_t szA  = (rowBase + ar0 < M) ? 16u : 0u;
    const size_t gA0 = (size_t)(rowBase + ar0) * DIM + ak0 * 8;
    const size_t gA1 = gA0 + 8;

    uint32_t soB[4]; size_t gB[4];
#pragma unroll
    for (int i = 0; i < 4; i++) {
        int idx = i * 256 + tid;
        int br = idx >> 2, bk4 = idx & 3;
        soB[i] = (uint32_t)(br * PITCH + bk4 * 16);
        gB[i] = (size_t)(nBase + br) * DIM + bk4 * 8;
    }

    const uint32_t aOff = (uint32_t)((warpRow * 64 + (lane & 7) + ((lane >> 3) & 1) * 8) * PITCH
                                     + (lane >> 4) * 16);
    const uint32_t bOff = (uint32_t)((warpCol * 64 + (lane >> 4) * 8 + (lane & 7)) * PITCH
                                     + ((lane >> 3) & 1) * 16);

    float acc[4][8][4];
#pragma unroll
    for (int f = 0; f < 4; f++)
#pragma unroll
        for (int g = 0; g < 8; g++)
#pragma unroll
            for (int i = 0; i < 4; i++) acc[f][g][i] = 0.0f;

    auto load_stage = [&](int chunk, int buf) {
        const int k0 = chunk * BK;
        const uint32_t st = sb + (uint32_t)buf * STAGE_SZ;
        CP_ASYNC(st + soA0,           Ah + gA0 + k0, szA);
        CP_ASYNC(st + soA1,           Ah + gA1 + k0, szA);
        CP_ASYNC(st + SZ_AT + soA0,   Al + gA0 + k0, szA);
        CP_ASYNC(st + SZ_AT + soA1,   Al + gA1 + k0, szA);
#pragma unroll
        for (int i = 0; i < 4; i++) {
            CP_ASYNC(st + 2 * SZ_AT + soB[i],         Bh + gB[i] + k0, 16u);
            CP_ASYNC(st + 2 * SZ_AT + SZ_BT + soB[i], Bl + gB[i] + k0, 16u);
        }
        CP_COMMIT();
    };

    load_stage(0, 0);
    load_stage(1, 1);

    int buf = 0;
    for (int c = 0; c < KCHUNKS; c++) {
        if (c + 1 < KCHUNKS)
            asm volatile("cp.async.wait_group 1;" ::: "memory");
        else
            asm volatile("cp.async.wait_group 0;" ::: "memory");
        __syncthreads();

        if (c + 2 < KCHUNKS) {
            int nb = buf + 2; if (nb >= NSTAGE) nb -= NSTAGE;
            load_stage(c + 2, nb);
        }

        const uint32_t st = sb + (uint32_t)buf * STAGE_SZ;
#pragma unroll
        for (int ks = 0; ks < 2; ks++) {
            const uint32_t kb = (uint32_t)(ks * 32);
            uint32_t aH[4][4], aL[4][4], bH[8][2], bL[8][2];
#pragma unroll
            for (int f = 0; f < 4; f++) {
                LDMATRIX_X4(aH[f][0], aH[f][1], aH[f][2], aH[f][3],
                            st + aOff + (uint32_t)(f * 16 * PITCH) + kb);
                LDMATRIX_X4(aL[f][0], aL[f][1], aL[f][2], aL[f][3],
                            st + SZ_AT + aOff + (uint32_t)(f * 16 * PITCH) + kb);
            }
#pragma unroll
            for (int p = 0; p < 4; p++) {
                LDMATRIX_X4(bH[2 * p][0], bH[2 * p][1], bH[2 * p + 1][0], bH[2 * p + 1][1],
                            st + 2 * SZ_AT + bOff + (uint32_t)(p * 16 * PITCH) + kb);
                LDMATRIX_X4(bL[2 * p][0], bL[2 * p][1], bL[2 * p + 1][0], bL[2 * p + 1][1],
                            st + 2 * SZ_AT + SZ_BT + bOff + (uint32_t)(p * 16 * PITCH) + kb);
            }
#pragma unroll
            for (int f = 0; f < 4; f++)
#pragma unroll
                for (int g = 0; g < 8; g++) {
                    MMA_BF16(acc[f][g], aH[f][0], aH[f][1], aH[f][2], aH[f][3],
                             bH[g][0], bH[g][1]);
                    MMA_BF16(acc[f][g], aH[f][0], aH[f][1], aH[f][2], aH[f][3],
                             bL[g][0], bL[g][1]);
                    MMA_BF16(acc[f][g], aL[f][0], aL[f][1], aL[f][2], aL[f][3],
                             bH[g][0], bH[g][1]);
                }
        }
        buf++; if (buf >= NSTAGE) buf -= NSTAGE;
    }

#pragma unroll
    for (int f = 0; f < 4; f++) {
        const int r0 = rowBase + warpRow * 64 + f * 16 + (lane >> 2);
#pragma unroll
        for (int g = 0; g < 8; g++) {
            const int col = nBase + warpCol * 64 + g * 8 + (lane & 3) * 2;
            const float2 b = *(const float2*)(bias + col);
            if (r0 < M) {
                float2 o = make_float2(acc[f][g][0] + b.x, acc[f][g][1] + b.y);
                *(float2*)(C + (size_t)r0 * ldc + col) = o;
            }
            if (r0 + 8 < M) {
                float2 o = make_float2(acc[f][g][2] + b.x, acc[f][g][3] + b.y);
                *(float2*)(C + (size_t)(r0 + 8) * ldc + col) = o;
            }
        }
    }
}

// =================== weight transpose + bf16 split ===================
__global__ void transpose_split(const float* __restrict__ in,
                                __nv_bfloat16* __restrict__ oh,
                                __nv_bfloat16* __restrict__ ol) {
    __shared__ float t[32][33];
    int bx = blockIdx.x * 32, by = blockIdx.y * 32;
    int x = bx + threadIdx.x;
#pragma unroll
    for (int j = 0; j < 32; j += 8)
        t[threadIdx.y + j][threadIdx.x] = in[(size_t)(by + threadIdx.y + j) * DIM + x];
    __syncthreads();
    int x2 = by + threadIdx.x;
#pragma unroll
    for (int j = 0; j < 32; j += 8) {
        float v = t[threadIdx.x][threadIdx.y + j];
        __nv_bfloat16 h, l; bf16_split(v, h, l);
        size_t o = (size_t)(bx + threadIdx.y + j) * DIM + x2;
        oh[o] = h; ol[o] = l;
    }
}

// =================== fp32 -> bf16 hi/lo split ===================
__global__ void split_arr(const float* __restrict__ in,
                          __nv_bfloat16* __restrict__ oh,
                          __nv_bfloat16* __restrict__ ol, int n4) {
    int i = blockIdx.x * blockDim.x + threadIdx.x;
    if (i >= n4) return;
    float4 v = ((const float4*)in)[i];
    __nv_bfloat16 h0, l0, h1, l1, h2, l2, h3, l3;
    bf16_split(v.x, h0, l0); bf16_split(v.y, h1, l1);
    bf16_split(v.z, h2, l2); bf16_split(v.w, h3, l3);
    __nv_bfloat162 hA{h0, h1}, hB{h2, h3}, lA{l0, l1}, lB{l2, l3};
    ((__nv_bfloat162*)oh)[2 * i] = hA; ((__nv_bfloat162*)oh)[2 * i + 1] = hB;
    ((__nv_bfloat162*)ol)[2 * i] = lA; ((__nv_bfloat162*)ol)[2 * i + 1] = lB;
}

// =================== bias concat ===================
__global__ void concat_bias(const float* __restrict__ bk,
                            const float* __restrict__ bq,
                            const float* __restrict__ bv) {
    int i = blockIdx.x * blockDim.x + threadIdx.x;
    if (i < DIM) {
        g_bias[i] = bk[i];
        g_bias[DIM + i] = bq[i];
        g_bias[2 * DIM + i] = bv[i];
    }
}

// =================== CSR build ===================
__global__ void zero_csr() {
    int i = blockIdx.x * blockDim.x + threadIdx.x;
    if (i <= NODES) g_cnt[i] = 0;
    if (i < NODES)  g_fill[i] = 0;
}
__global__ void hist_recv(const int* __restrict__ recv) {
    int e = blockIdx.x * blockDim.x + threadIdx.x;
    if (e < EDGES) atomicAdd(&g_cnt[recv[e] + 1], 1);
}
#define SCAN_T 1024
#define SCHUNK 25
__global__ void __launch_bounds__(SCAN_T) scan_offsets() {
    __shared__ int sums[SCAN_T];
    int t = threadIdx.x;
    int base = t * SCHUNK;
    int vals[SCHUNK];
    int s = 0;
#pragma unroll
    for (int i = 0; i < SCHUNK; i++) {
        int idx = base + i;
        vals[i] = (idx <= NODES) ? g_cnt[idx] : 0;
        s += vals[i];
    }
    sums[t] = s;
    __syncthreads();
    for (int d = 1; d < SCAN_T; d <<= 1) {
        int v = (t >= d) ? sums[t - d] : 0;
        __syncthreads();
        sums[t] += v;
        __syncthreads();
    }
    int run = (t > 0) ? sums[t - 1] : 0;
#pragma unroll
    for (int i = 0; i < SCHUNK; i++) {
        run += vals[i];
        int idx = base + i;
        if (idx <= NODES) g_cnt[idx] = run;
    }
}
__global__ void scatter_csr(const int* __restrict__ send,
                            const int* __restrict__ recv) {
    int e = blockIdx.x * blockDim.x + threadIdx.x;
    if (e >= EDGES) return;
    int r = recv[e];
    int pos = g_cnt[r] + atomicAdd(&g_fill[r], 1);
    g_esend[pos] = send[e];
}

// =================== fused node attention + aggregation =====================
__global__ void __launch_bounds__(256) node_attn_agg() {
    int gw = (blockIdx.x * blockDim.x + threadIdx.x) >> 5;
    if (gw >= NODES) return;
    const int lane = threadIdx.x & 31;
    const int r = gw;

    const float4* qp = (const float4*)&g_KQV[(size_t)r * NKQV + DIM + lane * 16];
    float4 q0 = qp[0], q1 = qp[1], q2 = qp[2], q3 = qp[3];

    const int beg = g_cnt[r], end = g_cnt[r + 1];
    float denom = 0.0f;
    float4 a0 = {0, 0, 0, 0}, a1 = {0, 0, 0, 0}, a2 = {0, 0, 0, 0}, a3 = {0, 0, 0, 0};

    for (int j = beg; j < end; j++) {
        int s = g_esend[j];
        const float4* kp = (const float4*)&g_KQV[(size_t)s * NKQV + lane * 16];
        const float4* vp = (const float4*)&g_KQV[(size_t)s * NKQV + 2 * DIM + lane * 16];
        float4 k0 = kp[0], k1 = kp[1], k2 = kp[2], k3 = kp[3];
        float4 v0 = vp[0], v1 = vp[1], v2 = vp[2], v3 = vp[3];
        float d = q0.x * k0.x + q0.y * k0.y + q0.z * k0.z + q0.w * k0.w
                + q1.x * k1.x + q1.y * k1.y + q1.z * k1.z + q1.w * k1.w
                + q2.x * k2.x + q2.y * k2.y + q2.z * k2.z + q2.w * k2.w
                + q3.x * k3.x + q3.y * k3.y + q3.z * k3.z + q3.w * k3.w;
        d += __shfl_xor_sync(0xffffffffu, d, 1);
        d += __shfl_xor_sync(0xffffffffu, d, 2);
        float w = __expf(d * 0.125f);
        denom += w;
        a0.x += w * v0.x; a0.y += w * v0.y; a0.z += w * v0.z; a0.w += w * v0.w;
        a1.x += w * v1.x; a1.y += w * v1.y; a1.z += w * v1.z; a1.w += w * v1.w;
        a2.x += w * v2.x; a2.y += w * v2.y; a2.z += w * v2.z; a2.w += w * v2.w;
        a3.x += w * v3.x; a3.y += w * v3.y; a3.z += w * v3.z; a3.w += w * v3.w;
    }

    float inv = (denom > 0.0f) ? 1.0f / denom : 0.0f;
    float vals[16] = {a0.x * inv, a0.y * inv, a0.z * inv, a0.w * inv,
                      a1.x * inv, a1.y * inv, a1.z * inv, a1.w * inv,
                      a2.x * inv, a2.y * inv, a2.z * inv, a2.w * inv,
                      a3.x * inv, a3.y * inv, a3.z * inv, a3.w * inv};
    __nv_bfloat162 hp[8], lp[8];
#pragma unroll
    for (int i = 0; i < 8; i++) {
        __nv_bfloat16 h0, l0, h1, l1;
        bf16_split(vals[2 * i], h0, l0);
        bf16_split(vals[2 * i + 1], h1, l1);
        hp[i] = __nv_bfloat162{h0, h1};
        lp[i] = __nv_bfloat162{l0, l1};
    }
    uint4* dh = (uint4*)&g_GH[(size_t)r * DIM + lane * 16];
    uint4* dl = (uint4*)&g_GL[(size_t)r * DIM + lane * 16];
    dh[0] = ((const uint4*)hp)[0];
    dh[1] = ((const uint4*)hp)[1];
    dl[0] = ((const uint4*)lp)[0];
    dl[1] = ((const uint4*)lp)[1];
}

// ---------------------------------------------------------------------------
extern "C" void kernel_launch(void* const* d_in, const int* in_sizes, int n_in,
                              void* d_out, int out_size) {
    const float* x   = (const float*)d_in[0];
    const int*  eidx = (const int*)  d_in[1];
    const float* Wk  = (const float*)d_in[2];
    const float* bk  = (const float*)d_in[3];
    const float* Wq  = (const float*)d_in[4];
    const float* bq  = (const float*)d_in[5];
    const float* Wv  = (const float*)d_in[6];
    const float* bv  = (const float*)d_in[7];
    const float* Wff = (const float*)d_in[8];
    const float* bff = (const float*)d_in[9];
    float* out = (float*)d_out;

    const int* send = eidx;
    const int* recv = eidx + EDGES;

    float *KQVp, *biasp;
    __nv_bfloat16 *XH, *XL, *GH, *GL, *WTH, *WTL;
    cudaGetSymbolAddress((void**)&KQVp, g_KQV);
    cudaGetSymbolAddress((void**)&biasp, g_bias);
    cudaGetSymbolAddress((void**)&XH,  g_XH);
    cudaGetSymbolAddress((void**)&XL,  g_XL);
    cudaGetSymbolAddress((void**)&GH,  g_GH);
    cudaGetSymbolAddress((void**)&GL,  g_GL);
    cudaGetSymbolAddress((void**)&WTH, g_WTH);
    cudaGetSymbolAddress((void**)&WTL, g_WTL);

    cudaFuncSetAttribute(gemm_bf16x3,
        cudaFuncAttributeMaxDynamicSharedMemorySize, SMEM_TOTAL);

    dim3 tgrid(16, 16), tblk(32, 8);
    transpose_split<<<tgrid, tblk>>>(Wk,  WTH + 0 * DIM * DIM, WTL + 0 * DIM * DIM);
    transpose_split<<<tgrid, tblk>>>(Wq,  WTH + 1 * DIM * DIM, WTL + 1 * DIM * DIM);
    transpose_split<<<tgrid, tblk>>>(Wv,  WTH + 2 * DIM * DIM, WTL + 2 * DIM * DIM);
    transpose_split<<<tgrid, tblk>>>(Wff, WTH + 3 * DIM * DIM, WTL + 3 * DIM * DIM);
    concat_bias<<<2, 256>>>(bk, bq, bv);

    const int n4 = NODES * DIM / 4;
    split_arr<<<(n4 + 255) / 256, 256>>>(x, XH, XL, n4);

    zero_csr<<<(NODES + 256) / 256, 256>>>();
    hist_recv<<<(EDGES + 255) / 256, 256>>>(recv);
    scan_offsets<<<1, SCAN_T>>>();
    scatter_csr<<<(EDGES + 255) / 256, 256>>>(send, recv);

    dim3 gkqv(NKQV / BN, (NODES + BM - 1) / BM);   // (6, 196)
    gemm_bf16x3<<<gkqv, 256, SMEM_TOTAL>>>(XH, XL, WTH, WTL, biasp,
                                           KQVp, NODES, NKQV);

    node_attn_agg<<<(NODES * 32 + 255) / 256, 256>>>();

    dim3 gff(DIM / BN, (NODES + BM - 1) / BM);     // (2, 196)
    gemm_bf16x3<<<gff, 256, SMEM_TOTAL>>>(GH, GL, WTH + 3 * DIM * DIM,
                                          WTL + 3 * DIM * DIM, bff, out,
                                          NODES, DIM);
}

// round 6
// speedup vs baseline: 3.3031x; 1.2364x over previous
#include <cuda_runtime.h>
#include <cuda_fp16.h>
#include <cstdint>

#define NODES 25000
#define EDGES 150000
#define DIM   512
#define NKQV  1536
#define HEADS 8

// ---------------- scratch (device globals) ----------------
__device__ __align__(256) float g_KQV[NODES * NKQV];          // [node][K|Q|V]
__device__ __align__(256) __half g_XF[NODES * DIM];           // x as fp16
__device__ __align__(256) __half g_GF[NODES * DIM];           // agg as fp16
__device__ __align__(256) __half g_WTH[4 * DIM * DIM];        // W^T hi [N][K]
__device__ __align__(256) __half g_WTL[4 * DIM * DIM];        // W^T lo
__device__ __align__(256) float g_bias[NKQV];
// CSR
__device__ int g_cnt[NODES + 1];
__device__ int g_fill[NODES];
__device__ int g_esend[EDGES];

// =================== helpers ===================
__device__ __forceinline__ uint32_t smem_u32(const void* p) {
    uint32_t a;
    asm("{ .reg .u64 t; cvta.to.shared.u64 t, %1; cvt.u32.u64 %0, t; }"
        : "=r"(a) : "l"(p));
    return a;
}

#define CP_ASYNC(dst, src, sz) \
    asm volatile("cp.async.cg.shared.global [%0], [%1], 16, %2;" \
                 :: "r"(dst), "l"(src), "r"(sz) : "memory")
#define CP_COMMIT() asm volatile("cp.async.commit_group;" ::: "memory")

#define LDMATRIX_X4(r0, r1, r2, r3, a) \
    asm volatile("ldmatrix.sync.aligned.m8n8.x4.shared.b16 {%0,%1,%2,%3}, [%4];" \
                 : "=r"(r0), "=r"(r1), "=r"(r2), "=r"(r3) : "r"(a))

#define MMA_F16(d, a0, a1, a2, a3, b0, b1)                                    \
    asm volatile("mma.sync.aligned.m16n8k16.row.col.f32.f16.f16.f32 "         \
                 "{%0,%1,%2,%3}, {%4,%5,%6,%7}, {%8,%9}, {%0,%1,%2,%3};"      \
                 : "+f"((d)[0]), "+f"((d)[1]), "+f"((d)[2]), "+f"((d)[3])     \
                 : "r"(a0), "r"(a1), "r"(a2), "r"(a3), "r"(b0), "r"(b1))

// =================== fp16 weight-split GEMM =================================
// C[M,N] = A_f16[M,512] @ (Bh + Bl)^T + bias (BT: [N][512] row-major fp16).
// CTA 128x256, 8 warps (2x4), warp tile 64x64, BK=32, 4-stage cp.async.
#define BM 128
#define BN 256
#define BK 32
#define KCHUNKS (DIM / BK)
#define PITCH 80                       // 32 fp16 (64B) + 16B pad
#define SZ_AT (128 * PITCH)            // 10240
#define SZ_BT (256 * PITCH)            // 20480
#define STAGE_SZ (SZ_AT + 2 * SZ_BT)   // A, Bh, Bl = 51200
#define NSTAGE 4
#define SMEM_TOTAL (NSTAGE * STAGE_SZ) // 204800

__global__ void __launch_bounds__(256, 1) gemm_f16w(
    const __half* __restrict__ A,
    const __half* __restrict__ Bh, const __half* __restrict__ Bl,
    const float* __restrict__ bias, float* __restrict__ C, int M, int ldc)
{
    extern __shared__ char smem[];
    const uint32_t sb = smem_u32(smem);
    const int tid = threadIdx.x, wid = tid >> 5, lane = tid & 31;
    const int warpRow = wid & 1, warpCol = wid >> 1;      // 2 x 4
    const int rowBase = blockIdx.y * BM;
    const int nBase = blockIdx.x * BN;

    // A: 512 16B-chunks -> 2/thread. B: 1024/half -> 4/thread each half.
    const int ar0 = tid >> 1, ak0 = (tid & 1) * 2;
    const uint32_t soA0 = (uint32_t)(ar0 * PITCH + ak0 * 16);
    const uint32_t soA1 = soA0 + 16;
    const uint32_t szA  = (rowBase + ar0 < M) ? 16u : 0u;
    const size_t gA0 = (size_t)(rowBase + ar0) * DIM + ak0 * 8;
    const size_t gA1 = gA0 + 8;

    uint32_t soB[4]; size_t gB[4];
#pragma unroll
    for (int i = 0; i < 4; i++) {
        int idx = i * 256 + tid;
        int br = idx >> 2, bk4 = idx & 3;
        soB[i] = (uint32_t)(br * PITCH + bk4 * 16);
        gB[i] = (size_t)(nBase + br) * DIM + bk4 * 8;
    }

    const uint32_t aOff = (uint32_t)((warpRow * 64 + (lane & 7) + ((lane >> 3) & 1) * 8) * PITCH
                                     + (lane >> 4) * 16);
    const uint32_t bOff = (uint32_t)((warpCol * 64 + (lane >> 4) * 8 + (lane & 7)) * PITCH
                                     + ((lane >> 3) & 1) * 16);

    float acc[4][8][4];
#pragma unroll
    for (int f = 0; f < 4; f++)
#pragma unroll
        for (int g = 0; g < 8; g++)
#pragma unroll
            for (int i = 0; i < 4; i++) acc[f][g][i] = 0.0f;

    auto load_stage = [&](int chunk, int buf) {
        const int k0 = chunk * BK;
        const uint32_t st = sb + (uint32_t)buf * STAGE_SZ;
        CP_ASYNC(st + soA0, A + gA0 + k0, szA);
        CP_ASYNC(st + soA1, A + gA1 + k0, szA);
#pragma unroll
        for (int i = 0; i < 4; i++) {
            CP_ASYNC(st + SZ_AT + soB[i],         Bh + gB[i] + k0, 16u);
            CP_ASYNC(st + SZ_AT + SZ_BT + soB[i], Bl + gB[i] + k0, 16u);
        }
        CP_COMMIT();
    };

    load_stage(0, 0);
    load_stage(1, 1);
    load_stage(2, 2);

    int buf = 0;
    for (int c = 0; c < KCHUNKS; c++) {
        if (c + 1 >= KCHUNKS)
            asm volatile("cp.async.wait_group 0;" ::: "memory");
        else if (c + 2 >= KCHUNKS)
            asm volatile("cp.async.wait_group 1;" ::: "memory");
        else
            asm volatile("cp.async.wait_group 2;" ::: "memory");
        __syncthreads();

        if (c + 3 < KCHUNKS) {
            int nb = buf + 3; if (nb >= NSTAGE) nb -= NSTAGE;
            load_stage(c + 3, nb);
        }

        const uint32_t st = sb + (uint32_t)buf * STAGE_SZ;
#pragma unroll
        for (int ks = 0; ks < 2; ks++) {
            const uint32_t kb = (uint32_t)(ks * 32);
            uint32_t aF[4][4], bH[8][2], bL[8][2];
#pragma unroll
            for (int f = 0; f < 4; f++)
                LDMATRIX_X4(aF[f][0], aF[f][1], aF[f][2], aF[f][3],
                            st + aOff + (uint32_t)(f * 16 * PITCH) + kb);
#pragma unroll
            for (int p = 0; p < 4; p++) {
                LDMATRIX_X4(bH[2 * p][0], bH[2 * p][1], bH[2 * p + 1][0], bH[2 * p + 1][1],
                            st + SZ_AT + bOff + (uint32_t)(p * 16 * PITCH) + kb);
                LDMATRIX_X4(bL[2 * p][0], bL[2 * p][1], bL[2 * p + 1][0], bL[2 * p + 1][1],
                            st + SZ_AT + SZ_BT + bOff + (uint32_t)(p * 16 * PITCH) + kb);
            }
#pragma unroll
            for (int f = 0; f < 4; f++)
#pragma unroll
                for (int g = 0; g < 8; g++) {
                    MMA_F16(acc[f][g], aF[f][0], aF[f][1], aF[f][2], aF[f][3],
                            bH[g][0], bH[g][1]);
                    MMA_F16(acc[f][g], aF[f][0], aF[f][1], aF[f][2], aF[f][3],
                            bL[g][0], bL[g][1]);
                }
        }
        buf++; if (buf >= NSTAGE) buf -= NSTAGE;
    }

#pragma unroll
    for (int f = 0; f < 4; f++) {
        const int r0 = rowBase + warpRow * 64 + f * 16 + (lane >> 2);
#pragma unroll
        for (int g = 0; g < 8; g++) {
            const int col = nBase + warpCol * 64 + g * 8 + (lane & 3) * 2;
            const float2 b = *(const float2*)(bias + col);
            if (r0 < M) {
                float2 o = make_float2(acc[f][g][0] + b.x, acc[f][g][1] + b.y);
                *(float2*)(C + (size_t)r0 * ldc + col) = o;
            }
            if (r0 + 8 < M) {
                float2 o = make_float2(acc[f][g][2] + b.x, acc[f][g][3] + b.y);
                *(float2*)(C + (size_t)(r0 + 8) * ldc + col) = o;
            }
        }
    }
}

// =================== weight transpose + fp16 split ===================
__global__ void transpose_split(const float* __restrict__ in,
                                __half* __restrict__ oh,
                                __half* __restrict__ ol) {
    __shared__ float t[32][33];
    int bx = blockIdx.x * 32, by = blockIdx.y * 32;
    int x = bx + threadIdx.x;
#pragma unroll
    for (int j = 0; j < 32; j += 8)
        t[threadIdx.y + j][threadIdx.x] = in[(size_t)(by + threadIdx.y + j) * DIM + x];
    __syncthreads();
    int x2 = by + threadIdx.x;
#pragma unroll
    for (int j = 0; j < 32; j += 8) {
        float v = t[threadIdx.x][threadIdx.y + j];
        __half h = __float2half_rn(v);
        __half l = __float2half_rn(v - __half2float(h));
        size_t o = (size_t)(bx + threadIdx.y + j) * DIM + x2;
        oh[o] = h; ol[o] = l;
    }
}

// =================== fp32 -> fp16 cast (8 elems/thread) ===================
__global__ void cast_f16(const float* __restrict__ in,
                         __half* __restrict__ out, int n8) {
    int i = blockIdx.x * blockDim.x + threadIdx.x;
    if (i >= n8) return;
    float4 v0 = ((const float4*)in)[2 * i];
    float4 v1 = ((const float4*)in)[2 * i + 1];
    __half2 h[4];
    h[0] = __floats2half2_rn(v0.x, v0.y);
    h[1] = __floats2half2_rn(v0.z, v0.w);
    h[2] = __floats2half2_rn(v1.x, v1.y);
    h[3] = __floats2half2_rn(v1.z, v1.w);
    ((uint4*)out)[i] = *(const uint4*)h;
}

// =================== bias concat ===================
__global__ void concat_bias(const float* __restrict__ bk,
                            const float* __restrict__ bq,
                            const float* __restrict__ bv) {
    int i = blockIdx.x * blockDim.x + threadIdx.x;
    if (i < DIM) {
        g_bias[i] = bk[i];
        g_bias[DIM + i] = bq[i];
        g_bias[2 * DIM + i] = bv[i];
    }
}

// =================== CSR build ===================
__global__ void zero_csr() {
    int i = blockIdx.x * blockDim.x + threadIdx.x;
    if (i <= NODES) g_cnt[i] = 0;
    if (i < NODES)  g_fill[i] = 0;
}
__global__ void hist_recv(const int* __restrict__ recv) {
    int e = blockIdx.x * blockDim.x + threadIdx.x;
    if (e < EDGES) atomicAdd(&g_cnt[recv[e] + 1], 1);
}
#define SCAN_T 1024
#define SCHUNK 25
__global__ void __launch_bounds__(SCAN_T) scan_offsets() {
    __shared__ int sums[SCAN_T];
    int t = threadIdx.x;
    int base = t * SCHUNK;
    int vals[SCHUNK];
    int s = 0;
#pragma unroll
    for (int i = 0; i < SCHUNK; i++) {
        int idx = base + i;
        vals[i] = (idx <= NODES) ? g_cnt[idx] : 0;
        s += vals[i];
    }
    sums[t] = s;
    __syncthreads();
    for (int d = 1; d < SCAN_T; d <<= 1) {
        int v = (t >= d) ? sums[t - d] : 0;
        __syncthreads();
        sums[t] += v;
        __syncthreads();
    }
    int run = (t > 0) ? sums[t - 1] : 0;
#pragma unroll
    for (int i = 0; i < SCHUNK; i++) {
        run += vals[i];
        int idx = base + i;
        if (idx <= NODES) g_cnt[idx] = run;
    }
}
__global__ void scatter_csr(const int* __restrict__ send,
                            const int* __restrict__ recv) {
    int e = blockIdx.x * blockDim.x + threadIdx.x;
    if (e >= EDGES) return;
    int r = recv[e];
    int pos = g_cnt[r] + atomicAdd(&g_fill[r], 1);
    g_esend[pos] = send[e];
}

// =================== fused node attention + aggregation =====================
__global__ void __launch_bounds__(256) node_attn_agg() {
    int gw = (blockIdx.x * blockDim.x + threadIdx.x) >> 5;
    if (gw >= NODES) return;
    const int lane = threadIdx.x & 31;
    const int r = gw;

    const float4* qp = (const float4*)&g_KQV[(size_t)r * NKQV + DIM + lane * 16];
    float4 q0 = qp[0], q1 = qp[1], q2 = qp[2], q3 = qp[3];

    const int beg = g_cnt[r], end = g_cnt[r + 1];
    float denom = 0.0f;
    float4 a0 = {0, 0, 0, 0}, a1 = {0, 0, 0, 0}, a2 = {0, 0, 0, 0}, a3 = {0, 0, 0, 0};

    for (int j = beg; j < end; j++) {
        int s = g_esend[j];
        const float4* kp = (const float4*)&g_KQV[(size_t)s * NKQV + lane * 16];
        const float4* vp = (const float4*)&g_KQV[(size_t)s * NKQV + 2 * DIM + lane * 16];
        float4 k0 = kp[0], k1 = kp[1], k2 = kp[2], k3 = kp[3];
        float4 v0 = vp[0], v1 = vp[1], v2 = vp[2], v3 = vp[3];
        float d = q0.x * k0.x + q0.y * k0.y + q0.z * k0.z + q0.w * k0.w
                + q1.x * k1.x + q1.y * k1.y + q1.z * k1.z + q1.w * k1.w
                + q2.x * k2.x + q2.y * k2.y + q2.z * k2.z + q2.w * k2.w
                + q3.x * k3.x + q3.y * k3.y + q3.z * k3.z + q3.w * k3.w;
        d += __shfl_xor_sync(0xffffffffu, d, 1);
        d += __shfl_xor_sync(0xffffffffu, d, 2);
        float w = __expf(d * 0.125f);
        denom += w;
        a0.x += w * v0.x; a0.y += w * v0.y; a0.z += w * v0.z; a0.w += w * v0.w;
        a1.x += w * v1.x; a1.y += w * v1.y; a1.z += w * v1.z; a1.w += w * v1.w;
        a2.x += w * v2.x; a2.y += w * v2.y; a2.z += w * v2.z; a2.w += w * v2.w;
        a3.x += w * v3.x; a3.y += w * v3.y; a3.z += w * v3.z; a3.w += w * v3.w;
    }

    float inv = (denom > 0.0f) ? 1.0f / denom : 0.0f;
    float vals[16] = {a0.x * inv, a0.y * inv, a0.z * inv, a0.w * inv,
                      a1.x * inv, a1.y * inv, a1.z * inv, a1.w * inv,
                      a2.x * inv, a2.y * inv, a2.z * inv, a2.w * inv,
                      a3.x * inv, a3.y * inv, a3.z * inv, a3.w * inv};
    __half2 hp[8];
#pragma unroll
    for (int i = 0; i < 8; i++)
        hp[i] = __floats2half2_rn(vals[2 * i], vals[2 * i + 1]);
    ((uint4*)&g_GF[(size_t)r * DIM + lane * 16])[0] = ((const uint4*)hp)[0];
    ((uint4*)&g_GF[(size_t)r * DIM + lane * 16])[1] = ((const uint4*)hp)[1];
}

// ---------------------------------------------------------------------------
extern "C" void kernel_launch(void* const* d_in, const int* in_sizes, int n_in,
                              void* d_out, int out_size) {
    const float* x   = (const float*)d_in[0];
    const int*  eidx = (const int*)  d_in[1];
    const float* Wk  = (const float*)d_in[2];
    const float* bk  = (const float*)d_in[3];
    const float* Wq  = (const float*)d_in[4];
    const float* bq  = (const float*)d_in[5];
    const float* Wv  = (const float*)d_in[6];
    const float* bv  = (const float*)d_in[7];
    const float* Wff = (const float*)d_in[8];
    const float* bff = (const float*)d_in[9];
    float* out = (float*)d_out;

    const int* send = eidx;
    const int* recv = eidx + EDGES;

    float *KQVp, *biasp;
    __half *XF, *GF, *WTH, *WTL;
    cudaGetSymbolAddress((void**)&KQVp, g_KQV);
    cudaGetSymbolAddress((void**)&biasp, g_bias);
    cudaGetSymbolAddress((void**)&XF,  g_XF);
    cudaGetSymbolAddress((void**)&GF,  g_GF);
    cudaGetSymbolAddress((void**)&WTH, g_WTH);
    cudaGetSymbolAddress((void**)&WTL, g_WTL);

    cudaFuncSetAttribute(gemm_f16w,
        cudaFuncAttributeMaxDynamicSharedMemorySize, SMEM_TOTAL);

    dim3 tgrid(16, 16), tblk(32, 8);
    transpose_split<<<tgrid, tblk>>>(Wk,  WTH + 0 * DIM * DIM, WTL + 0 * DIM * DIM);
    transpose_split<<<tgrid, tblk>>>(Wq,  WTH + 1 * DIM * DIM, WTL + 1 * DIM * DIM);
    transpose_split<<<tgrid, tblk>>>(Wv,  WTH + 2 * DIM * DIM, WTL + 2 * DIM * DIM);
    transpose_split<<<tgrid, tblk>>>(Wff, WTH + 3 * DIM * DIM, WTL + 3 * DIM * DIM);
    concat_bias<<<2, 256>>>(bk, bq, bv);

    const int n8 = NODES * DIM / 8;
    cast_f16<<<(n8 + 255) / 256, 256>>>(x, XF, n8);

    zero_csr<<<(NODES + 256) / 256, 256>>>();
    hist_recv<<<(EDGES + 255) / 256, 256>>>(recv);
    scan_offsets<<<1, SCAN_T>>>();
    scatter_csr<<<(EDGES + 255) / 256, 256>>>(send, recv);

    dim3 gkqv(NKQV / BN, (NODES + BM - 1) / BM);   // (6, 196)
    gemm_f16w<<<gkqv, 256, SMEM_TOTAL>>>(XF, WTH, WTL, biasp, KQVp, NODES, NKQV);

    node_attn_agg<<<(NODES * 32 + 255) / 256, 256>>>();

    dim3 gff(DIM / BN, (NODES + BM - 1) / BM);     // (2, 196)
    gemm_f16w<<<gff, 256, SMEM_TOTAL>>>(GF, WTH + 3 * DIM * DIM,
                                        WTL + 3 * DIM * DIM, bff, out,
                                        NODES, DIM);
}

// round 7
// speedup vs baseline: 3.7511x; 1.1356x over previous
#include <cuda_runtime.h>
#include <cuda_fp16.h>
#include <cstdint>

#define NODES 25000
#define EDGES 150000
#define DIM   512
#define NKQV  1536
#define HEADS 8

// ---------------- scratch (device globals) ----------------
__device__ __align__(256) float g_KQV[NODES * NKQV];          // [node][K|Q|V]
__device__ __align__(256) __half g_XF[NODES * DIM];           // x as fp16
__device__ __align__(256) __half g_GF[NODES * DIM];           // agg as fp16
__device__ __align__(256) __half g_WTH[4 * DIM * DIM];        // W^T hi [N][K]
__device__ __align__(256) __half g_WTL[4 * DIM * DIM];        // W^T lo
__device__ __align__(256) float g_bias[NKQV];
// CSR
__device__ int g_cnt[NODES + 1];
__device__ int g_fill[NODES];
__device__ int g_esend[EDGES];

// =================== helpers ===================
__device__ __forceinline__ uint32_t smem_u32(const void* p) {
    uint32_t a;
    asm("{ .reg .u64 t; cvta.to.shared.u64 t, %1; cvt.u32.u64 %0, t; }"
        : "=r"(a) : "l"(p));
    return a;
}

#define CP_ASYNC(dst, src, sz) \
    asm volatile("cp.async.cg.shared.global [%0], [%1], 16, %2;" \
                 :: "r"(dst), "l"(src), "r"(sz) : "memory")
#define CP_COMMIT() asm volatile("cp.async.commit_group;" ::: "memory")
#define CP_WAIT(n)  asm volatile("cp.async.wait_group %0;" :: "n"(n) : "memory")

#define LDMATRIX_X4(r0, r1, r2, r3, a) \
    asm volatile("ldmatrix.sync.aligned.m8n8.x4.shared.b16 {%0,%1,%2,%3}, [%4];" \
                 : "=r"(r0), "=r"(r1), "=r"(r2), "=r"(r3) : "r"(a))

#define MMA_F16(d, a0, a1, a2, a3, b0, b1)                                    \
    asm volatile("mma.sync.aligned.m16n8k16.row.col.f32.f16.f16.f32 "         \
                 "{%0,%1,%2,%3}, {%4,%5,%6,%7}, {%8,%9}, {%0,%1,%2,%3};"      \
                 : "+f"((d)[0]), "+f"((d)[1]), "+f"((d)[2]), "+f"((d)[3])     \
                 : "r"(a0), "r"(a1), "r"(a2), "r"(a3), "r"(b0), "r"(b1))

// =================== fp16 GEMM, TERMS = 1 or 2 weight terms =================
// C[M,N] = A_f16[M,512] @ (Bh [+ Bl])^T + bias. CTA 128x256, 8 warps, BK=32.
#define BM 128
#define BN 256
#define BK 32
#define KCHUNKS (DIM / BK)
#define PITCH 80
#define SZ_AT (128 * PITCH)            // 10240
#define SZ_BT (256 * PITCH)            // 20480

template <int TERMS, int NST>
__global__ void __launch_bounds__(256, 1) gemm_f16(
    const __half* __restrict__ A,
    const __half* __restrict__ Bh, const __half* __restrict__ Bl,
    const float* __restrict__ bias, float* __restrict__ C, int M, int ldc)
{
    constexpr uint32_t STAGE = SZ_AT + TERMS * SZ_BT;
    extern __shared__ char smem[];
    const uint32_t sb = smem_u32(smem);
    const int tid = threadIdx.x, wid = tid >> 5, lane = tid & 31;
    const int warpRow = wid & 1, warpCol = wid >> 1;      // 2 x 4
    const int rowBase = blockIdx.y * BM;
    const int nBase = blockIdx.x * BN;

    const int ar0 = tid >> 1, ak0 = (tid & 1) * 2;
    const uint32_t soA0 = (uint32_t)(ar0 * PITCH + ak0 * 16);
    const uint32_t soA1 = soA0 + 16;
    const uint32_t szA  = (rowBase + ar0 < M) ? 16u : 0u;
    const size_t gA0 = (size_t)(rowBase + ar0) * DIM + ak0 * 8;
    const size_t gA1 = gA0 + 8;

    uint32_t soB[4]; size_t gB[4];
#pragma unroll
    for (int i = 0; i < 4; i++) {
        int idx = i * 256 + tid;
        int br = idx >> 2, bk4 = idx & 3;
        soB[i] = (uint32_t)(br * PITCH + bk4 * 16);
        gB[i] = (size_t)(nBase + br) * DIM + bk4 * 8;
    }

    const uint32_t aOff = (uint32_t)((warpRow * 64 + (lane & 7) + ((lane >> 3) & 1) * 8) * PITCH
                                     + (lane >> 4) * 16);
    const uint32_t bOff = (uint32_t)((warpCol * 64 + (lane >> 4) * 8 + (lane & 7)) * PITCH
                                     + ((lane >> 3) & 1) * 16);

    float acc[4][8][4];
#pragma unroll
    for (int f = 0; f < 4; f++)
#pragma unroll
        for (int g = 0; g < 8; g++)
#pragma unroll
            for (int i = 0; i < 4; i++) acc[f][g][i] = 0.0f;

    auto load_stage = [&](int chunk, int buf) {
        const int k0 = chunk * BK;
        const uint32_t st = sb + (uint32_t)buf * STAGE;
        CP_ASYNC(st + soA0, A + gA0 + k0, szA);
        CP_ASYNC(st + soA1, A + gA1 + k0, szA);
#pragma unroll
        for (int i = 0; i < 4; i++) {
            CP_ASYNC(st + SZ_AT + soB[i], Bh + gB[i] + k0, 16u);
            if (TERMS == 2)
                CP_ASYNC(st + SZ_AT + SZ_BT + soB[i], Bl + gB[i] + k0, 16u);
        }
        CP_COMMIT();
    };

#pragma unroll
    for (int s = 0; s < NST - 1; s++) load_stage(s, s);

    int buf = 0;
    for (int c = 0; c < KCHUNKS; c++) {
        int n = KCHUNKS - 1 - c; if (n > NST - 2) n = NST - 2;
        switch (n) {
            case 0: CP_WAIT(0); break;
            case 1: CP_WAIT(1); break;
            case 2: CP_WAIT(2); break;
            case 3: CP_WAIT(3); break;
            default: CP_WAIT(4); break;
        }
        __syncthreads();

        if (c + NST - 1 < KCHUNKS) {
            int nb = buf + NST - 1; if (nb >= NST) nb -= NST;
            load_stage(c + NST - 1, nb);
        }

        const uint32_t st = sb + (uint32_t)buf * STAGE;
#pragma unroll
        for (int ks = 0; ks < 2; ks++) {
            const uint32_t kb = (uint32_t)(ks * 32);
            uint32_t aF[4][4], bH[8][2], bL[8][2];
#pragma unroll
            for (int f = 0; f < 4; f++)
                LDMATRIX_X4(aF[f][0], aF[f][1], aF[f][2], aF[f][3],
                            st + aOff + (uint32_t)(f * 16 * PITCH) + kb);
#pragma unroll
            for (int p = 0; p < 4; p++) {
                LDMATRIX_X4(bH[2 * p][0], bH[2 * p][1], bH[2 * p + 1][0], bH[2 * p + 1][1],
                            st + SZ_AT + bOff + (uint32_t)(p * 16 * PITCH) + kb);
                if (TERMS == 2)
                    LDMATRIX_X4(bL[2 * p][0], bL[2 * p][1], bL[2 * p + 1][0], bL[2 * p + 1][1],
                                st + SZ_AT + SZ_BT + bOff + (uint32_t)(p * 16 * PITCH) + kb);
            }
#pragma unroll
            for (int f = 0; f < 4; f++)
#pragma unroll
                for (int g = 0; g < 8; g++) {
                    MMA_F16(acc[f][g], aF[f][0], aF[f][1], aF[f][2], aF[f][3],
                            bH[g][0], bH[g][1]);
                    if (TERMS == 2)
                        MMA_F16(acc[f][g], aF[f][0], aF[f][1], aF[f][2], aF[f][3],
                                bL[g][0], bL[g][1]);
                }
        }
        buf++; if (buf >= NST) buf -= NST;
    }

#pragma unroll
    for (int f = 0; f < 4; f++) {
        const int r0 = rowBase + warpRow * 64 + f * 16 + (lane >> 2);
#pragma unroll
        for (int g = 0; g < 8; g++) {
            const int col = nBase + warpCol * 64 + g * 8 + (lane & 3) * 2;
            const float2 b = *(const float2*)(bias + col);
            if (r0 < M) {
                float2 o = make_float2(acc[f][g][0] + b.x, acc[f][g][1] + b.y);
                *(float2*)(C + (size_t)r0 * ldc + col) = o;
            }
            if (r0 + 8 < M) {
                float2 o = make_float2(acc[f][g][2] + b.x, acc[f][g][3] + b.y);
                *(float2*)(C + (size_t)(r0 + 8) * ldc + col) = o;
            }
        }
    }
}

#define STAGE1 (SZ_AT + SZ_BT)
#define STAGE2 (SZ_AT + 2 * SZ_BT)
#define NST1 6
#define NST2 4
#define SMEM1 (NST1 * STAGE1)   // 184320
#define SMEM2 (NST2 * STAGE2)   // 204800

// =================== all-4 weight transpose + fp16 split (one launch) ======
__global__ void transpose_split4(const float* __restrict__ w0,
                                 const float* __restrict__ w1,
                                 const float* __restrict__ w2,
                                 const float* __restrict__ w3) {
    const float* in = (blockIdx.z == 0) ? w0 : (blockIdx.z == 1) ? w1
                    : (blockIdx.z == 2) ? w2 : w3;
    __half* oh = g_WTH + (size_t)blockIdx.z * DIM * DIM;
    __half* ol = g_WTL + (size_t)blockIdx.z * DIM * DIM;
    __shared__ float t[32][33];
    int bx = blockIdx.x * 32, by = blockIdx.y * 32;
    int x = bx + threadIdx.x;
#pragma unroll
    for (int j = 0; j < 32; j += 8)
        t[threadIdx.y + j][threadIdx.x] = in[(size_t)(by + threadIdx.y + j) * DIM + x];
    __syncthreads();
    int x2 = by + threadIdx.x;
#pragma unroll
    for (int j = 0; j < 32; j += 8) {
        float v = t[threadIdx.x][threadIdx.y + j];
        __half h = __float2half_rn(v);
        __half l = __float2half_rn(v - __half2float(h));
        size_t o = (size_t)(bx + threadIdx.y + j) * DIM + x2;
        oh[o] = h; ol[o] = l;
    }
}

// =================== prep: cast x, zero csr, concat bias ===================
__global__ void prep_misc(const float* __restrict__ x,
                          const float* __restrict__ bk,
                          const float* __restrict__ bq,
                          const float* __restrict__ bv) {
    int i = blockIdx.x * blockDim.x + threadIdx.x;
    const int n8 = NODES * DIM / 8;
    if (i < n8) {
        float4 v0 = ((const float4*)x)[2 * i];
        float4 v1 = ((const float4*)x)[2 * i + 1];
        __half2 h[4];
        h[0] = __floats2half2_rn(v0.x, v0.y);
        h[1] = __floats2half2_rn(v0.z, v0.w);
        h[2] = __floats2half2_rn(v1.x, v1.y);
        h[3] = __floats2half2_rn(v1.z, v1.w);
        ((uint4*)g_XF)[i] = *(const uint4*)h;
    }
    if (i <= NODES) g_cnt[i] = 0;
    if (i < NODES)  g_fill[i] = 0;
    if (i < DIM) {
        g_bias[i] = bk[i];
        g_bias[DIM + i] = bq[i];
        g_bias[2 * DIM + i] = bv[i];
    }
}

// =================== CSR build ===================
__global__ void hist_recv(const int* __restrict__ recv) {
    int e = blockIdx.x * blockDim.x + threadIdx.x;
    if (e < EDGES) atomicAdd(&g_cnt[recv[e] + 1], 1);
}
#define SCAN_T 1024
#define SCHUNK 25
__global__ void __launch_bounds__(SCAN_T) scan_offsets() {
    __shared__ int sums[SCAN_T];
    int t = threadIdx.x;
    int base = t * SCHUNK;
    int vals[SCHUNK];
    int s = 0;
#pragma unroll
    for (int i = 0; i < SCHUNK; i++) {
        int idx = base + i;
        vals[i] = (idx <= NODES) ? g_cnt[idx] : 0;
        s += vals[i];
    }
    sums[t] = s;
    __syncthreads();
    for (int d = 1; d < SCAN_T; d <<= 1) {
        int v = (t >= d) ? sums[t - d] : 0;
        __syncthreads();
        sums[t] += v;
        __syncthreads();
    }
    int run = (t > 0) ? sums[t - 1] : 0;
#pragma unroll
    for (int i = 0; i < SCHUNK; i++) {
        run += vals[i];
        int idx = base + i;
        if (idx <= NODES) g_cnt[idx] = run;
    }
}
__global__ void scatter_csr(const int* __restrict__ send,
                            const int* __restrict__ recv) {
    int e = blockIdx.x * blockDim.x + threadIdx.x;
    if (e >= EDGES) return;
    int r = recv[e];
    int pos = g_cnt[r] + atomicAdd(&g_fill[r], 1);
    g_esend[pos] = send[e];
}

// =================== fused node attention + aggregation =====================
// Warp per node; 2-edge software pipeline for memory-level parallelism.
__global__ void __launch_bounds__(256) node_attn_agg() {
    int gw = (blockIdx.x * blockDim.x + threadIdx.x) >> 5;
    if (gw >= NODES) return;
    const int lane = threadIdx.x & 31;
    const int r = gw;

    const float4* qp = (const float4*)&g_KQV[(size_t)r * NKQV + DIM + lane * 16];
    float4 q0 = qp[0], q1 = qp[1], q2 = qp[2], q3 = qp[3];

    const int beg = g_cnt[r], end = g_cnt[r + 1];
    float denom = 0.0f;
    float4 a0 = {0, 0, 0, 0}, a1 = {0, 0, 0, 0}, a2 = {0, 0, 0, 0}, a3 = {0, 0, 0, 0};

    int j = beg;
    for (; j + 1 < end; j += 2) {
        int s0 = g_esend[j], s1 = g_esend[j + 1];
        const float4* kp0 = (const float4*)&g_KQV[(size_t)s0 * NKQV + lane * 16];
        const float4* vp0 = (const float4*)&g_KQV[(size_t)s0 * NKQV + 2 * DIM + lane * 16];
        const float4* kp1 = (const float4*)&g_KQV[(size_t)s1 * NKQV + lane * 16];
        const float4* vp1 = (const float4*)&g_KQV[(size_t)s1 * NKQV + 2 * DIM + lane * 16];
        float4 k00 = kp0[0], k01 = kp0[1], k02 = kp0[2], k03 = kp0[3];
        float4 k10 = kp1[0], k11 = kp1[1], k12 = kp1[2], k13 = kp1[3];
        float4 v00 = vp0[0], v01 = vp0[1], v02 = vp0[2], v03 = vp0[3];
        float4 v10 = vp1[0], v11 = vp1[1], v12 = vp1[2], v13 = vp1[3];

        float d0 = q0.x * k00.x + q0.y * k00.y + q0.z * k00.z + q0.w * k00.w
                 + q1.x * k01.x + q1.y * k01.y + q1.z * k01.z + q1.w * k01.w
                 + q2.x * k02.x + q2.y * k02.y + q2.z * k02.z + q2.w * k02.w
                 + q3.x * k03.x + q3.y * k03.y + q3.z * k03.z + q3.w * k03.w;
        float d1 = q0.x * k10.x + q0.y * k10.y + q0.z * k10.z + q0.w * k10.w
                 + q1.x * k11.x + q1.y * k11.y + q1.z * k11.z + q1.w * k11.w
                 + q2.x * k12.x + q2.y * k12.y + q2.z * k12.z + q2.w * k12.w
                 + q3.x * k13.x + q3.y * k13.y + q3.z * k13.z + q3.w * k13.w;
        d0 += __shfl_xor_sync(0xffffffffu, d0, 1);
        d1 += __shfl_xor_sync(0xffffffffu, d1, 1);
        d0 += __shfl_xor_sync(0xffffffffu, d0, 2);
        d1 += __shfl_xor_sync(0xffffffffu, d1, 2);
        float w0 = __expf(d0 * 0.125f);
        float w1 = __expf(d1 * 0.125f);
        denom += w0 + w1;
        a0.x += w0 * v00.x + w1 * v10.x; a0.y += w0 * v00.y + w1 * v10.y;
        a0.z += w0 * v00.z + w1 * v10.z; a0.w += w0 * v00.w + w1 * v10.w;
        a1.x += w0 * v01.x + w1 * v11.x; a1.y += w0 * v01.y + w1 * v11.y;
        a1.z += w0 * v01.z + w1 * v11.z; a1.w += w0 * v01.w + w1 * v11.w;
        a2.x += w0 * v02.x + w1 * v12.x; a2.y += w0 * v02.y + w1 * v12.y;
        a2.z += w0 * v02.z + w1 * v12.z; a2.w += w0 * v02.w + w1 * v12.w;
        a3.x += w0 * v03.x + w1 * v13.x; a3.y += w0 * v03.y + w1 * v13.y;
        a3.z += w0 * v03.z + w1 * v13.z; a3.w += w0 * v03.w + w1 * v13.w;
    }
    if (j < end) {
        int s = g_esend[j];
        const float4* kp = (const float4*)&g_KQV[(size_t)s * NKQV + lane * 16];
        const float4* vp = (const float4*)&g_KQV[(size_t)s * NKQV + 2 * DIM + lane * 16];
        float4 k0 = kp[0], k1 = kp[1], k2 = kp[2], k3 = kp[3];
        float4 v0 = vp[0], v1 = vp[1], v2 = vp[2], v3 = vp[3];
        float d = q0.x * k0.x + q0.y * k0.y + q0.z * k0.z + q0.w * k0.w
                + q1.x * k1.x + q1.y * k1.y + q1.z * k1.z + q1.w * k1.w
                + q2.x * k2.x + q2.y * k2.y + q2.z * k2.z + q2.w * k2.w
                + q3.x * k3.x + q3.y * k3.y + q3.z * k3.z + q3.w * k3.w;
        d += __shfl_xor_sync(0xffffffffu, d, 1);
        d += __shfl_xor_sync(0xffffffffu, d, 2);
        float w = __expf(d * 0.125f);
        denom += w;
        a0.x += w * v0.x; a0.y += w * v0.y; a0.z += w * v0.z; a0.w += w * v0.w;
        a1.x += w * v1.x; a1.y += w * v1.y; a1.z += w * v1.z; a1.w += w * v1.w;
        a2.x += w * v2.x; a2.y += w * v2.y; a2.z += w * v2.z; a2.w += w * v2.w;
        a3.x += w * v3.x; a3.y += w * v3.y; a3.z += w * v3.z; a3.w += w * v3.w;
    }

    float inv = (denom > 0.0f) ? 1.0f / denom : 0.0f;
    float vals[16] = {a0.x * inv, a0.y * inv, a0.z * inv, a0.w * inv,
                      a1.x * inv, a1.y * inv, a1.z * inv, a1.w * inv,
                      a2.x * inv, a2.y * inv, a2.z * inv, a2.w * inv,
                      a3.x * inv, a3.y * inv, a3.z * inv, a3.w * inv};
    __half2 hp[8];
#pragma unroll
    for (int i = 0; i < 8; i++)
        hp[i] = __floats2half2_rn(vals[2 * i], vals[2 * i + 1]);
    ((uint4*)&g_GF[(size_t)r * DIM + lane * 16])[0] = ((const uint4*)hp)[0];
    ((uint4*)&g_GF[(size_t)r * DIM + lane * 16])[1] = ((const uint4*)hp)[1];
}

// ---------------------------------------------------------------------------
extern "C" void kernel_launch(void* const* d_in, const int* in_sizes, int n_in,
                              void* d_out, int out_size) {
    const float* x   = (const float*)d_in[0];
    const int*  eidx = (const int*)  d_in[1];
    const float* Wk  = (const float*)d_in[2];
    const float* bk  = (const float*)d_in[3];
    const float* Wq  = (const float*)d_in[4];
    const float* bq  = (const float*)d_in[5];
    const float* Wv  = (const float*)d_in[6];
    const float* bv  = (const float*)d_in[7];
    const float* Wff = (const float*)d_in[8];
    const float* bff = (const float*)d_in[9];
    float* out = (float*)d_out;

    const int* send = eidx;
    const int* recv = eidx + EDGES;

    float *KQVp, *biasp;
    __half *XF, *GF, *WTH, *WTL;
    cudaGetSymbolAddress((void**)&KQVp, g_KQV);
    cudaGetSymbolAddress((void**)&biasp, g_bias);
    cudaGetSymbolAddress((void**)&XF,  g_XF);
    cudaGetSymbolAddress((void**)&GF,  g_GF);
    cudaGetSymbolAddress((void**)&WTH, g_WTH);
    cudaGetSymbolAddress((void**)&WTL, g_WTL);

    cudaFuncSetAttribute((const void*)gemm_f16<1, NST1>,
        cudaFuncAttributeMaxDynamicSharedMemorySize, SMEM1);
    cudaFuncSetAttribute((const void*)gemm_f16<2, NST2>,
        cudaFuncAttributeMaxDynamicSharedMemorySize, SMEM2);

    dim3 tgrid(16, 16, 4), tblk(32, 8);
    transpose_split4<<<tgrid, tblk>>>(Wk, Wq, Wv, Wff);

    const int n8 = NODES * DIM / 8;
    prep_misc<<<(n8 + 255) / 256, 256>>>(x, bk, bq, bv);

    hist_recv<<<(EDGES + 255) / 256, 256>>>(recv);
    scan_offsets<<<1, SCAN_T>>>();
    scatter_csr<<<(EDGES + 255) / 256, 256>>>(send, recv);

    // KQ GEMM: single-term fp16 (scores tolerate weight rounding)
    dim3 gkq(1024 / BN, (NODES + BM - 1) / BM);    // (4, 196)
    gemm_f16<1, NST1><<<gkq, 256, SMEM1>>>(XF, WTH, nullptr, biasp,
                                           KQVp, NODES, NKQV);
    // V GEMM: 2-term (output path needs precision)
    dim3 gv(512 / BN, (NODES + BM - 1) / BM);      // (2, 196)
    gemm_f16<2, NST2><<<gv, 256, SMEM2>>>(XF, WTH + 2 * DIM * DIM,
                                          WTL + 2 * DIM * DIM, biasp + 1024,
                                          KQVp + 1024, NODES, NKQV);

    node_attn_agg<<<(NODES * 32 + 255) / 256, 256>>>();

    // FF GEMM: 2-term
    dim3 gff(DIM / BN, (NODES + BM - 1) / BM);     // (2, 196)
    gemm_f16<2, NST2><<<gff, 256, SMEM2>>>(GF, WTH + 3 * DIM * DIM,
                                           WTL + 3 * DIM * DIM, bff, out,
                                           NODES, DIM);
}

// round 8
// speedup vs baseline: 4.6119x; 1.2295x over previous
#include <cuda_runtime.h>
#include <cuda_fp16.h>
#include <cstdint>

#define NODES 25000
#define EDGES 150000
#define DIM   512
#define HEADS 8

// ---------------- scratch (device globals) ----------------
// weight slots (transposed [N][K] fp16): 0=Wk, 1=Wv, 2=Wq, 3=Wff
__device__ __align__(256) __half g_WTH[4 * DIM * DIM];
__device__ __align__(256) __half g_WTL[4 * DIM * DIM];
__device__ __align__(256) __half g_KVh[NODES * 1024];   // [node][K(512)|V(512)] fp16
__device__ __align__(256) float  g_Qf[NODES * DIM];     // Q fp32
__device__ __align__(256) __half g_XF[NODES * DIM];     // x as fp16
__device__ __align__(256) __half g_GF[NODES * DIM];     // agg as fp16
__device__ __align__(256) float  g_bias[1536];          // [bk|bv|bq]
// CSR
__device__ int g_cnt[NODES + 1];
__device__ int g_fill[NODES];
__device__ int g_esend[EDGES];

// =================== helpers ===================
__device__ __forceinline__ uint32_t smem_u32(const void* p) {
    uint32_t a;
    asm("{ .reg .u64 t; cvta.to.shared.u64 t, %1; cvt.u32.u64 %0, t; }"
        : "=r"(a) : "l"(p));
    return a;
}

#define CP_ASYNC(dst, src, sz) \
    asm volatile("cp.async.cg.shared.global [%0], [%1], 16, %2;" \
                 :: "r"(dst), "l"(src), "r"(sz) : "memory")
#define CP_COMMIT() asm volatile("cp.async.commit_group;" ::: "memory")
#define CP_WAIT(n)  asm volatile("cp.async.wait_group %0;" :: "n"(n) : "memory")

#define LDMATRIX_X4(r0, r1, r2, r3, a) \
    asm volatile("ldmatrix.sync.aligned.m8n8.x4.shared.b16 {%0,%1,%2,%3}, [%4];" \
                 : "=r"(r0), "=r"(r1), "=r"(r2), "=r"(r3) : "r"(a))

#define MMA_F16(d, a0, a1, a2, a3, b0, b1)                                    \
    asm volatile("mma.sync.aligned.m16n8k16.row.col.f32.f16.f16.f32 "         \
                 "{%0,%1,%2,%3}, {%4,%5,%6,%7}, {%8,%9}, {%0,%1,%2,%3};"      \
                 : "+f"((d)[0]), "+f"((d)[1]), "+f"((d)[2]), "+f"((d)[3])     \
                 : "r"(a0), "r"(a1), "r"(a2), "r"(a3), "r"(b0), "r"(b1))

// =================== fp16 GEMM =================================
// C[M,N] = A_f16[M,512] @ (Bh [+ Bl])^T + bias. CTA 128x256, 8 warps, BK=32.
#define BM 128
#define BN 256
#define BK 32
#define KCHUNKS (DIM / BK)
#define PITCH 80
#define SZ_AT (128 * PITCH)            // 10240
#define SZ_BT (256 * PITCH)            // 20480

template <int TERMS, int NST, bool HOUT>
__global__ void __launch_bounds__(256, 1) gemm_f16(
    const __half* __restrict__ A,
    const __half* __restrict__ Bh, const __half* __restrict__ Bl,
    const float* __restrict__ bias, void* __restrict__ Cv, int M, int ldc)
{
    constexpr uint32_t STAGE = SZ_AT + TERMS * SZ_BT;
    extern __shared__ char smem[];
    const uint32_t sb = smem_u32(smem);
    const int tid = threadIdx.x, wid = tid >> 5, lane = tid & 31;
    const int warpRow = wid & 1, warpCol = wid >> 1;      // 2 x 4
    const int rowBase = blockIdx.y * BM;
    const int nBase = blockIdx.x * BN;

    const int ar0 = tid >> 1, ak0 = (tid & 1) * 2;
    const uint32_t soA0 = (uint32_t)(ar0 * PITCH + ak0 * 16);
    const uint32_t soA1 = soA0 + 16;
    const uint32_t szA  = (rowBase + ar0 < M) ? 16u : 0u;
    const size_t gA0 = (size_t)(rowBase + ar0) * DIM + ak0 * 8;
    const size_t gA1 = gA0 + 8;

    uint32_t soB[4]; size_t gB[4];
#pragma unroll
    for (int i = 0; i < 4; i++) {
        int idx = i * 256 + tid;
        int br = idx >> 2, bk4 = idx & 3;
        soB[i] = (uint32_t)(br * PITCH + bk4 * 16);
        gB[i] = (size_t)(nBase + br) * DIM + bk4 * 8;
    }

    const uint32_t aOff = (uint32_t)((warpRow * 64 + (lane & 7) + ((lane >> 3) & 1) * 8) * PITCH
                                     + (lane >> 4) * 16);
    const uint32_t bOff = (uint32_t)((warpCol * 64 + (lane >> 4) * 8 + (lane & 7)) * PITCH
                                     + ((lane >> 3) & 1) * 16);

    float acc[4][8][4];
#pragma unroll
    for (int f = 0; f < 4; f++)
#pragma unroll
        for (int g = 0; g < 8; g++)
#pragma unroll
            for (int i = 0; i < 4; i++) acc[f][g][i] = 0.0f;

    auto load_stage = [&](int chunk, int buf) {
        const int k0 = chunk * BK;
        const uint32_t st = sb + (uint32_t)buf * STAGE;
        CP_ASYNC(st + soA0, A + gA0 + k0, szA);
        CP_ASYNC(st + soA1, A + gA1 + k0, szA);
#pragma unroll
        for (int i = 0; i < 4; i++) {
            CP_ASYNC(st + SZ_AT + soB[i], Bh + gB[i] + k0, 16u);
            if (TERMS == 2)
                CP_ASYNC(st + SZ_AT + SZ_BT + soB[i], Bl + gB[i] + k0, 16u);
        }
        CP_COMMIT();
    };

#pragma unroll
    for (int s = 0; s < NST - 1; s++) load_stage(s, s);

    int buf = 0;
    for (int c = 0; c < KCHUNKS; c++) {
        int n = KCHUNKS - 1 - c; if (n > NST - 2) n = NST - 2;
        switch (n) {
            case 0: CP_WAIT(0); break;
            case 1: CP_WAIT(1); break;
            case 2: CP_WAIT(2); break;
            case 3: CP_WAIT(3); break;
            default: CP_WAIT(4); break;
        }
        __syncthreads();

        if (c + NST - 1 < KCHUNKS) {
            int nb = buf + NST - 1; if (nb >= NST) nb -= NST;
            load_stage(c + NST - 1, nb);
        }

        const uint32_t st = sb + (uint32_t)buf * STAGE;
#pragma unroll
        for (int ks = 0; ks < 2; ks++) {
            const uint32_t kb = (uint32_t)(ks * 32);
            uint32_t aF[4][4], bH[8][2], bL[8][2];
#pragma unroll
            for (int f = 0; f < 4; f++)
                LDMATRIX_X4(aF[f][0], aF[f][1], aF[f][2], aF[f][3],
                            st + aOff + (uint32_t)(f * 16 * PITCH) + kb);
#pragma unroll
            for (int p = 0; p < 4; p++) {
                LDMATRIX_X4(bH[2 * p][0], bH[2 * p][1], bH[2 * p + 1][0], bH[2 * p + 1][1],
                            st + SZ_AT + bOff + (uint32_t)(p * 16 * PITCH) + kb);
                if (TERMS == 2)
                    LDMATRIX_X4(bL[2 * p][0], bL[2 * p][1], bL[2 * p + 1][0], bL[2 * p + 1][1],
                                st + SZ_AT + SZ_BT + bOff + (uint32_t)(p * 16 * PITCH) + kb);
            }
#pragma unroll
            for (int f = 0; f < 4; f++)
#pragma unroll
                for (int g = 0; g < 8; g++) {
                    MMA_F16(acc[f][g], aF[f][0], aF[f][1], aF[f][2], aF[f][3],
                            bH[g][0], bH[g][1]);
                    if (TERMS == 2)
                        MMA_F16(acc[f][g], aF[f][0], aF[f][1], aF[f][2], aF[f][3],
                                bL[g][0], bL[g][1]);
                }
        }
        buf++; if (buf >= NST) buf -= NST;
    }

#pragma unroll
    for (int f = 0; f < 4; f++) {
        const int r0 = rowBase + warpRow * 64 + f * 16 + (lane >> 2);
#pragma unroll
        for (int g = 0; g < 8; g++) {
            const int col = nBase + warpCol * 64 + g * 8 + (lane & 3) * 2;
            const float2 b = *(const float2*)(bias + col);
            if (HOUT) {
                __half* Cp = (__half*)Cv;
                if (r0 < M)
                    *(__half2*)(Cp + (size_t)r0 * ldc + col) =
                        __floats2half2_rn(acc[f][g][0] + b.x, acc[f][g][1] + b.y);
                if (r0 + 8 < M)
                    *(__half2*)(Cp + (size_t)(r0 + 8) * ldc + col) =
                        __floats2half2_rn(acc[f][g][2] + b.x, acc[f][g][3] + b.y);
            } else {
                float* Cp = (float*)Cv;
                if (r0 < M)
                    *(float2*)(Cp + (size_t)r0 * ldc + col) =
                        make_float2(acc[f][g][0] + b.x, acc[f][g][1] + b.y);
                if (r0 + 8 < M)
                    *(float2*)(Cp + (size_t)(r0 + 8) * ldc + col) =
                        make_float2(acc[f][g][2] + b.x, acc[f][g][3] + b.y);
            }
        }
    }
}

#define STAGE1 (SZ_AT + SZ_BT)
#define STAGE2 (SZ_AT + 2 * SZ_BT)
#define NST1 6
#define NST2 4
#define SMEM1 (NST1 * STAGE1)   // 184320
#define SMEM2 (NST2 * STAGE2)   // 204800

// =================== all-4 weight transpose + fp16 split ===================
// slot order: 0=Wk, 1=Wv, 2=Wq, 3=Wff
__global__ void transpose_split4(const float* __restrict__ wk,
                                 const float* __restrict__ wv,
                                 const float* __restrict__ wq,
                                 const float* __restrict__ wff) {
    const float* in = (blockIdx.z == 0) ? wk : (blockIdx.z == 1) ? wv
                    : (blockIdx.z == 2) ? wq : wff;
    __half* oh = g_WTH + (size_t)blockIdx.z * DIM * DIM;
    __half* ol = g_WTL + (size_t)blockIdx.z * DIM * DIM;
    __shared__ float t[32][33];
    int bx = blockIdx.x * 32, by = blockIdx.y * 32;
    int x = bx + threadIdx.x;
#pragma unroll
    for (int j = 0; j < 32; j += 8)
        t[threadIdx.y + j][threadIdx.x] = in[(size_t)(by + threadIdx.y + j) * DIM + x];
    __syncthreads();
    int x2 = by + threadIdx.x;
#pragma unroll
    for (int j = 0; j < 32; j += 8) {
        float v = t[threadIdx.x][threadIdx.y + j];
        __half h = __float2half_rn(v);
        __half l = __float2half_rn(v - __half2float(h));
        size_t o = (size_t)(bx + threadIdx.y + j) * DIM + x2;
        oh[o] = h; ol[o] = l;
    }
}

// =================== prep: cast x, zero csr, concat bias [bk|bv|bq] ========
__global__ void prep_misc(const float* __restrict__ x,
                          const float* __restrict__ bk,
                          const float* __restrict__ bq,
                          const float* __restrict__ bv) {
    int i = blockIdx.x * blockDim.x + threadIdx.x;
    const int n8 = NODES * DIM / 8;
    if (i < n8) {
        float4 v0 = ((const float4*)x)[2 * i];
        float4 v1 = ((const float4*)x)[2 * i + 1];
        __half2 h[4];
        h[0] = __floats2half2_rn(v0.x, v0.y);
        h[1] = __floats2half2_rn(v0.z, v0.w);
        h[2] = __floats2half2_rn(v1.x, v1.y);
        h[3] = __floats2half2_rn(v1.z, v1.w);
        ((uint4*)g_XF)[i] = *(const uint4*)h;
    }
    if (i <= NODES) g_cnt[i] = 0;
    if (i < NODES)  g_fill[i] = 0;
    if (i < DIM) {
        g_bias[i] = bk[i];
        g_bias[DIM + i] = bv[i];
        g_bias[2 * DIM + i] = bq[i];
    }
}

// =================== CSR build ===================
__global__ void hist_recv(const int* __restrict__ recv) {
    int e = blockIdx.x * blockDim.x + threadIdx.x;
    if (e < EDGES) atomicAdd(&g_cnt[recv[e] + 1], 1);
}
#define SCAN_T 1024
#define SCHUNK 25
#define SCAN_SMEM ((NODES + 1 + SCAN_T) * 4)
__global__ void __launch_bounds__(SCAN_T) scan_offsets() {
    extern __shared__ int sm[];          // [0..NODES] data, then [SCAN_T] sums
    int* sums = sm + NODES + 1;
    int t = threadIdx.x;
    for (int i = t; i <= NODES; i += SCAN_T) sm[i] = g_cnt[i];
    __syncthreads();
    int base = t * SCHUNK;
    int s = 0;
#pragma unroll
    for (int i = 0; i < SCHUNK; i++) {
        int idx = base + i;
        if (idx <= NODES) { s += sm[idx]; sm[idx] = s; }
    }
    sums[t] = s;
    __syncthreads();
    for (int d = 1; d < SCAN_T; d <<= 1) {
        int v = (t >= d) ? sums[t - d] : 0;
        __syncthreads();
        sums[t] += v;
        __syncthreads();
    }
    int off = (t > 0) ? sums[t - 1] : 0;
    __syncthreads();
    for (int i = t; i <= NODES; i += SCAN_T) {
        // recompute owner offset: owner chunk = i / SCHUNK
        int owner = i / SCHUNK;
        int o = (owner > 0) ? sums[owner - 1] : 0;
        g_cnt[i] = sm[i] + o;
    }
    (void)off;
}
__global__ void scatter_csr(const int* __restrict__ send,
                            const int* __restrict__ recv) {
    int e = blockIdx.x * blockDim.x + threadIdx.x;
    if (e >= EDGES) return;
    int r = recv[e];
    int pos = g_cnt[r] + atomicAdd(&g_fill[r], 1);
    g_esend[pos] = send[e];
}

// =================== fused node attention + aggregation =====================
// Warp per node; Q fp32 (read once), K/V fp16 (L2-resident); fp32 math.
__device__ __forceinline__ void ld16h(const __half* p, float* f) {
    uint4 u0 = *(const uint4*)p;
    uint4 u1 = *(const uint4*)(p + 8);
    const __half2* h0 = (const __half2*)&u0;
    const __half2* h1 = (const __half2*)&u1;
#pragma unroll
    for (int i = 0; i < 4; i++) {
        float2 a = __half22float2(h0[i]);
        f[2 * i] = a.x; f[2 * i + 1] = a.y;
        float2 b = __half22float2(h1[i]);
        f[8 + 2 * i] = b.x; f[8 + 2 * i + 1] = b.y;
    }
}

__global__ void __launch_bounds__(256) node_attn_agg() {
    int gw = (blockIdx.x * blockDim.x + threadIdx.x) >> 5;
    if (gw >= NODES) return;
    const int lane = threadIdx.x & 31;
    const int r = gw;

    float q[16];
    {
        const float4* qp = (const float4*)&g_Qf[(size_t)r * DIM + lane * 16];
#pragma unroll
        for (int i = 0; i < 4; i++) {
            float4 v = qp[i];
            q[4 * i] = v.x; q[4 * i + 1] = v.y; q[4 * i + 2] = v.z; q[4 * i + 3] = v.w;
        }
    }

    const int beg = g_cnt[r], end = g_cnt[r + 1];
    float denom = 0.0f;
    float a[16];
#pragma unroll
    for (int i = 0; i < 16; i++) a[i] = 0.0f;

    int j = beg;
    for (; j + 1 < end; j += 2) {
        int s0 = g_esend[j], s1 = g_esend[j + 1];
        const __half* b0 = &g_KVh[(size_t)s0 * 1024 + lane * 16];
        const __half* b1 = &g_KVh[(size_t)s1 * 1024 + lane * 16];
        float k0[16], v0[16], k1[16], v1[16];
        ld16h(b0, k0); ld16h(b1, k1);
        ld16h(b0 + 512, v0); ld16h(b1 + 512, v1);

        float d0 = 0.f, d1 = 0.f;
#pragma unroll
        for (int i = 0; i < 16; i++) { d0 += q[i] * k0[i]; d1 += q[i] * k1[i]; }
        d0 += __shfl_xor_sync(0xffffffffu, d0, 1);
        d1 += __shfl_xor_sync(0xffffffffu, d1, 1);
        d0 += __shfl_xor_sync(0xffffffffu, d0, 2);
        d1 += __shfl_xor_sync(0xffffffffu, d1, 2);
        float w0 = __expf(d0 * 0.125f);
        float w1 = __expf(d1 * 0.125f);
        denom += w0 + w1;
#pragma unroll
        for (int i = 0; i < 16; i++) a[i] += w0 * v0[i] + w1 * v1[i];
    }
    if (j < end) {
        int s = g_esend[j];
        const __half* b = &g_KVh[(size_t)s * 1024 + lane * 16];
        float k[16], v[16];
        ld16h(b, k); ld16h(b + 512, v);
        float d = 0.f;
#pragma unroll
        for (int i = 0; i < 16; i++) d += q[i] * k[i];
        d += __shfl_xor_sync(0xffffffffu, d, 1);
        d += __shfl_xor_sync(0xffffffffu, d, 2);
        float w = __expf(d * 0.125f);
        denom += w;
#pragma unroll
        for (int i = 0; i < 16; i++) a[i] += w * v[i];
    }

    float inv = (denom > 0.0f) ? 1.0f / denom : 0.0f;
    __half2 hp[8];
#pragma unroll
    for (int i = 0; i < 8; i++)
        hp[i] = __floats2half2_rn(a[2 * i] * inv, a[2 * i + 1] * inv);
    ((uint4*)&g_GF[(size_t)r * DIM + lane * 16])[0] = ((const uint4*)hp)[0];
    ((uint4*)&g_GF[(size_t)r * DIM + lane * 16])[1] = ((const uint4*)hp)[1];
}

// ---------------------------------------------------------------------------
extern "C" void kernel_launch(void* const* d_in, const int* in_sizes, int n_in,
                              void* d_out, int out_size) {
    const float* x   = (const float*)d_in[0];
    const int*  eidx = (const int*)  d_in[1];
    const float* Wk  = (const float*)d_in[2];
    const float* bk  = (const float*)d_in[3];
    const float* Wq  = (const float*)d_in[4];
    const float* bq  = (const float*)d_in[5];
    const float* Wv  = (const float*)d_in[6];
    const float* bv  = (const float*)d_in[7];
    const float* Wff = (const float*)d_in[8];
    const float* bff = (const float*)d_in[9];
    float* out = (float*)d_out;

    const int* send = eidx;
    const int* recv = eidx + EDGES;

    float *Qf, *biasp;
    __half *XF, *GF, *KVh, *WTH, *WTL;
    cudaGetSymbolAddress((void**)&Qf,   g_Qf);
    cudaGetSymbolAddress((void**)&biasp, g_bias);
    cudaGetSymbolAddress((void**)&XF,  g_XF);
    cudaGetSymbolAddress((void**)&GF,  g_GF);
    cudaGetSymbolAddress((void**)&KVh, g_KVh);
    cudaGetSymbolAddress((void**)&WTH, g_WTH);
    cudaGetSymbolAddress((void**)&WTL, g_WTL);

    cudaFuncSetAttribute((const void*)gemm_f16<1, NST1, true>,
        cudaFuncAttributeMaxDynamicSharedMemorySize, SMEM1);
    cudaFuncSetAttribute((const void*)gemm_f16<1, NST1, false>,
        cudaFuncAttributeMaxDynamicSharedMemorySize, SMEM1);
    cudaFuncSetAttribute((const void*)gemm_f16<2, NST2, false>,
        cudaFuncAttributeMaxDynamicSharedMemorySize, SMEM2);
    cudaFuncSetAttribute((const void*)scan_offsets,
        cudaFuncAttributeMaxDynamicSharedMemorySize, SCAN_SMEM);

    dim3 tgrid(16, 16, 4), tblk(32, 8);
    transpose_split4<<<tgrid, tblk>>>(Wk, Wv, Wq, Wff);

    const int n8 = NODES * DIM / 8;
    prep_misc<<<(n8 + 255) / 256, 256>>>(x, bk, bq, bv);

    hist_recv<<<(EDGES + 255) / 256, 256>>>(recv);
    scan_offsets<<<1, SCAN_T, SCAN_SMEM>>>();
    scatter_csr<<<(EDGES + 255) / 256, 256>>>(send, recv);

    // KV GEMM: 1-term, fp16 out -> g_KVh [K|V], N=1024
    dim3 gkv(1024 / BN, (NODES + BM - 1) / BM);    // (4, 196)
    gemm_f16<1, NST1, true><<<gkv, 256, SMEM1>>>(XF, WTH, nullptr, biasp,
                                                 KVh, NODES, 1024);
    // Q GEMM: 1-term, fp32 out -> g_Qf, N=512
    dim3 gq(512 / BN, (NODES + BM - 1) / BM);      // (2, 196)
    gemm_f16<1, NST1, false><<<gq, 256, SMEM1>>>(XF, WTH + 2 * DIM * DIM,
                                                 nullptr, biasp + 1024,
                                                 Qf, NODES, DIM);

    node_attn_agg<<<(NODES * 32 + 255) / 256, 256>>>();

    // FF GEMM: 2-term, fp32 out
    dim3 gff(DIM / BN, (NODES + BM - 1) / BM);     // (2, 196)
    gemm_f16<2, NST2, false><<<gff, 256, SMEM2>>>(GF, WTH + 3 * DIM * DIM,
                                                  WTL + 3 * DIM * DIM, bff,
                                                  out, NODES, DIM);
}

// round 9
// speedup vs baseline: 5.5147x; 1.1958x over previous
#include <cuda_runtime.h>
#include <cuda_fp16.h>
#include <cstdint>

#define NODES 25000
#define EDGES 150000
#define DIM   512
#define NKVQ  1536
#define HEADS 8

// ---------------- scratch (device globals) ----------------
// weight slots (transposed [N][K] fp16): 0=Wk, 1=Wv, 2=Wq, 3=Wff
__device__ __align__(256) __half g_WT[4 * DIM * DIM];
__device__ __align__(256) __half g_KVQ[NODES * NKVQ];   // [node][K|V|Q] fp16
__device__ __align__(256) __half g_XF[NODES * DIM];     // x as fp16
__device__ __align__(256) __half g_GF[NODES * DIM];     // agg as fp16
__device__ __align__(256) float  g_bias[NKVQ];          // [bk|bv|bq]
// CSR
__device__ __align__(16) int g_cnt[NODES + 1];
__device__ int g_fill[NODES];
__device__ int g_esend[EDGES];

// =================== helpers ===================
__device__ __forceinline__ uint32_t smem_u32(const void* p) {
    uint32_t a;
    asm("{ .reg .u64 t; cvta.to.shared.u64 t, %1; cvt.u32.u64 %0, t; }"
        : "=r"(a) : "l"(p));
    return a;
}

#define CP_ASYNC(dst, src, sz) \
    asm volatile("cp.async.cg.shared.global [%0], [%1], 16, %2;" \
                 :: "r"(dst), "l"(src), "r"(sz) : "memory")
#define CP_COMMIT() asm volatile("cp.async.commit_group;" ::: "memory")
#define CP_WAIT(n)  asm volatile("cp.async.wait_group %0;" :: "n"(n) : "memory")

#define LDMATRIX_X4(r0, r1, r2, r3, a) \
    asm volatile("ldmatrix.sync.aligned.m8n8.x4.shared.b16 {%0,%1,%2,%3}, [%4];" \
                 : "=r"(r0), "=r"(r1), "=r"(r2), "=r"(r3) : "r"(a))

#define MMA_F16(d, a0, a1, a2, a3, b0, b1)                                    \
    asm volatile("mma.sync.aligned.m16n8k16.row.col.f32.f16.f16.f32 "         \
                 "{%0,%1,%2,%3}, {%4,%5,%6,%7}, {%8,%9}, {%0,%1,%2,%3};"      \
                 : "+f"((d)[0]), "+f"((d)[1]), "+f"((d)[2]), "+f"((d)[3])     \
                 : "r"(a0), "r"(a1), "r"(a2), "r"(a3), "r"(b0), "r"(b1))

// =================== fp16 GEMM (single weight term) =========================
// C[M,N] = A_f16[M,512] @ B^T + bias. CTA 128x256, 8 warps, BK=32, 6 stages.
#define BM 128
#define BN 256
#define BK 32
#define KCHUNKS (DIM / BK)
#define PITCH 80
#define SZ_AT (128 * PITCH)            // 10240
#define SZ_BT (256 * PITCH)            // 20480
#define STAGE (SZ_AT + SZ_BT)          // 30720
#define NST 6
#define SMEM_G (NST * STAGE)           // 184320

template <bool HOUT>
__global__ void __launch_bounds__(256, 1) gemm_f16(
    const __half* __restrict__ A, const __half* __restrict__ B,
    const float* __restrict__ bias, void* __restrict__ Cv, int M, int ldc)
{
    extern __shared__ char smem[];
    const uint32_t sb = smem_u32(smem);
    const int tid = threadIdx.x, wid = tid >> 5, lane = tid & 31;
    const int warpRow = wid & 1, warpCol = wid >> 1;      // 2 x 4
    const int rowBase = blockIdx.y * BM;
    const int nBase = blockIdx.x * BN;

    const int ar0 = tid >> 1, ak0 = (tid & 1) * 2;
    const uint32_t soA0 = (uint32_t)(ar0 * PITCH + ak0 * 16);
    const uint32_t soA1 = soA0 + 16;
    const uint32_t szA  = (rowBase + ar0 < M) ? 16u : 0u;
    const size_t gA0 = (size_t)(rowBase + ar0) * DIM + ak0 * 8;
    const size_t gA1 = gA0 + 8;

    uint32_t soB[4]; size_t gB[4];
#pragma unroll
    for (int i = 0; i < 4; i++) {
        int idx = i * 256 + tid;
        int br = idx >> 2, bk4 = idx & 3;
        soB[i] = (uint32_t)(br * PITCH + bk4 * 16);
        gB[i] = (size_t)(nBase + br) * DIM + bk4 * 8;
    }

    const uint32_t aOff = (uint32_t)((warpRow * 64 + (lane & 7) + ((lane >> 3) & 1) * 8) * PITCH
                                     + (lane >> 4) * 16);
    const uint32_t bOff = (uint32_t)((warpCol * 64 + (lane >> 4) * 8 + (lane & 7)) * PITCH
                                     + ((lane >> 3) & 1) * 16);

    float acc[4][8][4];
#pragma unroll
    for (int f = 0; f < 4; f++)
#pragma unroll
        for (int g = 0; g < 8; g++)
#pragma unroll
            for (int i = 0; i < 4; i++) acc[f][g][i] = 0.0f;

    auto load_stage = [&](int chunk, int buf) {
        const int k0 = chunk * BK;
        const uint32_t st = sb + (uint32_t)buf * STAGE;
        CP_ASYNC(st + soA0, A + gA0 + k0, szA);
        CP_ASYNC(st + soA1, A + gA1 + k0, szA);
#pragma unroll
        for (int i = 0; i < 4; i++)
            CP_ASYNC(st + SZ_AT + soB[i], B + gB[i] + k0, 16u);
        CP_COMMIT();
    };

#pragma unroll
    for (int s = 0; s < NST - 1; s++) load_stage(s, s);

    int buf = 0;
    for (int c = 0; c < KCHUNKS; c++) {
        int n = KCHUNKS - 1 - c; if (n > NST - 2) n = NST - 2;
        switch (n) {
            case 0: CP_WAIT(0); break;
            case 1: CP_WAIT(1); break;
            case 2: CP_WAIT(2); break;
            case 3: CP_WAIT(3); break;
            default: CP_WAIT(4); break;
        }
        __syncthreads();

        if (c + NST - 1 < KCHUNKS) {
            int nb = buf + NST - 1; if (nb >= NST) nb -= NST;
            load_stage(c + NST - 1, nb);
        }

        const uint32_t st = sb + (uint32_t)buf * STAGE;
#pragma unroll
        for (int ks = 0; ks < 2; ks++) {
            const uint32_t kb = (uint32_t)(ks * 32);
            uint32_t aF[4][4], bF[8][2];
#pragma unroll
            for (int f = 0; f < 4; f++)
                LDMATRIX_X4(aF[f][0], aF[f][1], aF[f][2], aF[f][3],
                            st + aOff + (uint32_t)(f * 16 * PITCH) + kb);
#pragma unroll
            for (int p = 0; p < 4; p++)
                LDMATRIX_X4(bF[2 * p][0], bF[2 * p][1], bF[2 * p + 1][0], bF[2 * p + 1][1],
                            st + SZ_AT + bOff + (uint32_t)(p * 16 * PITCH) + kb);
#pragma unroll
            for (int f = 0; f < 4; f++)
#pragma unroll
                for (int g = 0; g < 8; g++)
                    MMA_F16(acc[f][g], aF[f][0], aF[f][1], aF[f][2], aF[f][3],
                            bF[g][0], bF[g][1]);
        }
        buf++; if (buf >= NST) buf -= NST;
    }

#pragma unroll
    for (int f = 0; f < 4; f++) {
        const int r0 = rowBase + warpRow * 64 + f * 16 + (lane >> 2);
#pragma unroll
        for (int g = 0; g < 8; g++) {
            const int col = nBase + warpCol * 64 + g * 8 + (lane & 3) * 2;
            const float2 b = *(const float2*)(bias + col);
            if (HOUT) {
                __half* Cp = (__half*)Cv;
                if (r0 < M)
                    *(__half2*)(Cp + (size_t)r0 * ldc + col) =
                        __floats2half2_rn(acc[f][g][0] + b.x, acc[f][g][1] + b.y);
                if (r0 + 8 < M)
                    *(__half2*)(Cp + (size_t)(r0 + 8) * ldc + col) =
                        __floats2half2_rn(acc[f][g][2] + b.x, acc[f][g][3] + b.y);
            } else {
                float* Cp = (float*)Cv;
                if (r0 < M)
                    *(float2*)(Cp + (size_t)r0 * ldc + col) =
                        make_float2(acc[f][g][0] + b.x, acc[f][g][1] + b.y);
                if (r0 + 8 < M)
                    *(float2*)(Cp + (size_t)(r0 + 8) * ldc + col) =
                        make_float2(acc[f][g][2] + b.x, acc[f][g][3] + b.y);
            }
        }
    }
}

// =================== all-4 weight transpose -> fp16 (one launch) ============
// slot order: 0=Wk, 1=Wv, 2=Wq, 3=Wff
__global__ void transpose4(const float* __restrict__ wk,
                           const float* __restrict__ wv,
                           const float* __restrict__ wq,
                           const float* __restrict__ wff) {
    const float* in = (blockIdx.z == 0) ? wk : (blockIdx.z == 1) ? wv
                    : (blockIdx.z == 2) ? wq : wff;
    __half* oh = g_WT + (size_t)blockIdx.z * DIM * DIM;
    __shared__ float t[32][33];
    int bx = blockIdx.x * 32, by = blockIdx.y * 32;
    int x = bx + threadIdx.x;
#pragma unroll
    for (int j = 0; j < 32; j += 8)
        t[threadIdx.y + j][threadIdx.x] = in[(size_t)(by + threadIdx.y + j) * DIM + x];
    __syncthreads();
    int x2 = by + threadIdx.x;
#pragma unroll
    for (int j = 0; j < 32; j += 8)
        oh[(size_t)(bx + threadIdx.y + j) * DIM + x2] =
            __float2half_rn(t[threadIdx.x][threadIdx.y + j]);
}

// =================== prep: cast x, zero csr, concat bias [bk|bv|bq] ========
__global__ void prep_misc(const float* __restrict__ x,
                          const float* __restrict__ bk,
                          const float* __restrict__ bq,
                          const float* __restrict__ bv) {
    int i = blockIdx.x * blockDim.x + threadIdx.x;
    const int n8 = NODES * DIM / 8;
    if (i < n8) {
        float4 v0 = ((const float4*)x)[2 * i];
        float4 v1 = ((const float4*)x)[2 * i + 1];
        __half2 h[4];
        h[0] = __floats2half2_rn(v0.x, v0.y);
        h[1] = __floats2half2_rn(v0.z, v0.w);
        h[2] = __floats2half2_rn(v1.x, v1.y);
        h[3] = __floats2half2_rn(v1.z, v1.w);
        ((uint4*)g_XF)[i] = *(const uint4*)h;
    }
    if (i <= NODES) g_cnt[i] = 0;
    if (i < NODES)  g_fill[i] = 0;
    if (i < DIM) {
        g_bias[i] = bk[i];
        g_bias[DIM + i] = bv[i];
        g_bias[2 * DIM + i] = bq[i];
    }
}

// =================== CSR build ===================
__global__ void hist_recv(const int* __restrict__ recv) {
    int e = blockIdx.x * blockDim.x + threadIdx.x;
    if (e < EDGES) atomicAdd(&g_cnt[recv[e] + 1], 1);
}

// register-resident vectorized single-CTA scan: 1024 thr x 28 elems (int4 x 7)
#define SC_T 1024
#define SC_V 7
__global__ void __launch_bounds__(SC_T) scan_offsets() {
    __shared__ int wsum[32];
    const int t = threadIdx.x, lane = t & 31, wid = t >> 5;
    const int base = t * (SC_V * 4);
    int v[SC_V * 4];
#pragma unroll
    for (int i = 0; i < SC_V; i++) {
        int idx = base + i * 4;
        if (idx + 3 <= NODES) {
            int4 u = *(const int4*)&g_cnt[idx];
            v[4 * i] = u.x; v[4 * i + 1] = u.y; v[4 * i + 2] = u.z; v[4 * i + 3] = u.w;
        } else {
#pragma unroll
            for (int k = 0; k < 4; k++) {
                int id = idx + k;
                v[4 * i + k] = (id <= NODES) ? g_cnt[id] : 0;
            }
        }
    }
#pragma unroll
    for (int i = 1; i < SC_V * 4; i++) v[i] += v[i - 1];
    const int mytot = v[SC_V * 4 - 1];
    int inc = mytot;
#pragma unroll
    for (int d = 1; d < 32; d <<= 1) {
        int n = __shfl_up_sync(0xffffffffu, inc, d);
        if (lane >= d) inc += n;
    }
    if (lane == 31) wsum[wid] = inc;
    __syncthreads();
    if (wid == 0) {
        int s = wsum[lane];
#pragma unroll
        for (int d = 1; d < 32; d <<= 1) {
            int n = __shfl_up_sync(0xffffffffu, s, d);
            if (lane >= d) s += n;
        }
        wsum[lane] = s;
    }
    __syncthreads();
    const int off = (wid > 0 ? wsum[wid - 1] : 0) + (inc - mytot);
#pragma unroll
    for (int i = 0; i < SC_V; i++) {
        int idx = base + i * 4;
        if (idx + 3 <= NODES) {
            int4 u = make_int4(v[4 * i] + off, v[4 * i + 1] + off,
                               v[4 * i + 2] + off, v[4 * i + 3] + off);
            *(int4*)&g_cnt[idx] = u;
        } else {
#pragma unroll
            for (int k = 0; k < 4; k++) {
                int id = idx + k;
                if (id <= NODES) g_cnt[id] = v[4 * i + k] + off;
            }
        }
    }
}

__global__ void scatter_csr(const int* __restrict__ send,
                            const int* __restrict__ recv) {
    int e = blockIdx.x * blockDim.x + threadIdx.x;
    if (e >= EDGES) return;
    int r = recv[e];
    int pos = g_cnt[r] + atomicAdd(&g_fill[r], 1);
    g_esend[pos] = send[e];
}

// =================== fused node attention + aggregation =====================
// Warp per node; K/V/Q all fp16 (L2-resident); fp32 math.
__device__ __forceinline__ void ld16h(const __half* p, float* f) {
    uint4 u0 = *(const uint4*)p;
    uint4 u1 = *(const uint4*)(p + 8);
    const __half2* h0 = (const __half2*)&u0;
    const __half2* h1 = (const __half2*)&u1;
#pragma unroll
    for (int i = 0; i < 4; i++) {
        float2 a = __half22float2(h0[i]);
        f[2 * i] = a.x; f[2 * i + 1] = a.y;
        float2 b = __half22float2(h1[i]);
        f[8 + 2 * i] = b.x; f[8 + 2 * i + 1] = b.y;
    }
}

__global__ void __launch_bounds__(256) node_attn_agg() {
    int gw = (blockIdx.x * blockDim.x + threadIdx.x) >> 5;
    if (gw >= NODES) return;
    const int lane = threadIdx.x & 31;
    const int r = gw;

    float q[16];
    ld16h(&g_KVQ[(size_t)r * NKVQ + 1024 + lane * 16], q);

    const int beg = g_cnt[r], end = g_cnt[r + 1];
    float denom = 0.0f;
    float a[16];
#pragma unroll
    for (int i = 0; i < 16; i++) a[i] = 0.0f;

    int j = beg;
    for (; j + 1 < end; j += 2) {
        int s0 = g_esend[j], s1 = g_esend[j + 1];
        const __half* b0 = &g_KVQ[(size_t)s0 * NKVQ + lane * 16];
        const __half* b1 = &g_KVQ[(size_t)s1 * NKVQ + lane * 16];
        float k0[16], v0[16], k1[16], v1[16];
        ld16h(b0, k0); ld16h(b1, k1);
        ld16h(b0 + 512, v0); ld16h(b1 + 512, v1);

        float d0 = 0.f, d1 = 0.f;
#pragma unroll
        for (int i = 0; i < 16; i++) { d0 += q[i] * k0[i]; d1 += q[i] * k1[i]; }
        d0 += __shfl_xor_sync(0xffffffffu, d0, 1);
        d1 += __shfl_xor_sync(0xffffffffu, d1, 1);
        d0 += __shfl_xor_sync(0xffffffffu, d0, 2);
        d1 += __shfl_xor_sync(0xffffffffu, d1, 2);
        float w0 = __expf(d0 * 0.125f);
        float w1 = __expf(d1 * 0.125f);
        denom += w0 + w1;
#pragma unroll
        for (int i = 0; i < 16; i++) a[i] += w0 * v0[i] + w1 * v1[i];
    }
    if (j < end) {
        int s = g_esend[j];
        const __half* b = &g_KVQ[(size_t)s * NKVQ + lane * 16];
        float k[16], v[16];
        ld16h(b, k); ld16h(b + 512, v);
        float d = 0.f;
#pragma unroll
        for (int i = 0; i < 16; i++) d += q[i] * k[i];
        d += __shfl_xor_sync(0xffffffffu, d, 1);
        d += __shfl_xor_sync(0xffffffffu, d, 2);
        float w = __expf(d * 0.125f);
        denom += w;
#pragma unroll
        for (int i = 0; i < 16; i++) a[i] += w * v[i];
    }

    float inv = (denom > 0.0f) ? 1.0f / denom : 0.0f;
    __half2 hp[8];
#pragma unroll
    for (int i = 0; i < 8; i++)
        hp[i] = __floats2half2_rn(a[2 * i] * inv, a[2 * i + 1] * inv);
    ((uint4*)&g_GF[(size_t)r * DIM + lane * 16])[0] = ((const uint4*)hp)[0];
    ((uint4*)&g_GF[(size_t)r * DIM + lane * 16])[1] = ((const uint4*)hp)[1];
}

// ---------------------------------------------------------------------------
extern "C" void kernel_launch(void* const* d_in, const int* in_sizes, int n_in,
                              void* d_out, int out_size) {
    const float* x   = (const float*)d_in[0];
    const int*  eidx = (const int*)  d_in[1];
    const float* Wk  = (const float*)d_in[2];
    const float* bk  = (const float*)d_in[3];
    const float* Wq  = (const float*)d_in[4];
    const float* bq  = (const float*)d_in[5];
    const float* Wv  = (const float*)d_in[6];
    const float* bv  = (const float*)d_in[7];
    const float* Wff = (const float*)d_in[8];
    const float* bff = (const float*)d_in[9];
    float* out = (float*)d_out;

    const int* send = eidx;
    const int* recv = eidx + EDGES;

    float* biasp;
    __half *XF, *GF, *KVQ, *WT;
    cudaGetSymbolAddress((void**)&biasp, g_bias);
    cudaGetSymbolAddress((void**)&XF,  g_XF);
    cudaGetSymbolAddress((void**)&GF,  g_GF);
    cudaGetSymbolAddress((void**)&KVQ, g_KVQ);
    cudaGetSymbolAddress((void**)&WT,  g_WT);

    cudaFuncSetAttribute((const void*)gemm_f16<true>,
        cudaFuncAttributeMaxDynamicSharedMemorySize, SMEM_G);
    cudaFuncSetAttribute((const void*)gemm_f16<false>,
        cudaFuncAttributeMaxDynamicSharedMemorySize, SMEM_G);

    dim3 tgrid(16, 16, 4), tblk(32, 8);
    transpose4<<<tgrid, tblk>>>(Wk, Wv, Wq, Wff);

    const int n8 = NODES * DIM / 8;
    prep_misc<<<(n8 + 255) / 256, 256>>>(x, bk, bq, bv);

    hist_recv<<<(EDGES + 255) / 256, 256>>>(recv);
    scan_offsets<<<1, SC_T>>>();
    scatter_csr<<<(EDGES + 255) / 256, 256>>>(send, recv);

    // fused K|V|Q GEMM: 1-term, fp16 out, N=1536
    dim3 gkvq(NKVQ / BN, (NODES + BM - 1) / BM);   // (6, 196)
    gemm_f16<true><<<gkvq, 256, SMEM_G>>>(XF, WT, biasp, KVQ, NODES, NKVQ);

    node_attn_agg<<<(NODES * 32 + 255) / 256, 256>>>();

    // FF GEMM: 1-term, fp32 out
    dim3 gff(DIM / BN, (NODES + BM - 1) / BM);     // (2, 196)
    gemm_f16<false><<<gff, 256, SMEM_G>>>(GF, WT + 3 * DIM * DIM, bff,
                                          out, NODES, DIM);
}